// round 3
// baseline (speedup 1.0000x reference)
#include <cuda_runtime.h>

#define NB   2
#define NN   8192
#define NK   16
#define NH   4
#define ND   32
#define HD   128
#define CIN  64
#define COUT 128
#define NPTS (NB * NN)   // 16384
#define NCAT 384         // QA|KA|V concatenated

// ---------------- scratch (device globals; no allocations allowed) ----------
__device__ float g_Wcat[CIN * NCAT];   // [WqA1 | WkA1 | Wv]
__device__ float g_P2A1[3 * HD];
__device__ float g_c1[HD];
__device__ float g_QKV[NPTS * NCAT];   // per-point [QA(128) | KA(128) | V(128)]
__device__ float g_fused[NPTS * HD];

// ---------------- weight folding -------------------------------------------
__global__ void setup_kernel(const float* __restrict__ Wq, const float* __restrict__ Wk,
                             const float* __restrict__ Wv, const float* __restrict__ A1,
                             const float* __restrict__ P2, const float* __restrict__ b1,
                             const float* __restrict__ bp2) {
    int c = threadIdx.x;          // 0..383
    int r = blockIdx.x;
    if (r < CIN) {
        float acc;
        if (c < HD) {
            acc = 0.f;
            for (int j = 0; j < HD; j++) acc = fmaf(Wq[r * HD + j], A1[j * HD + c], acc);
        } else if (c < 2 * HD) {
            int cc = c - HD;
            acc = 0.f;
            for (int j = 0; j < HD; j++) acc = fmaf(Wk[r * HD + j], A1[j * HD + cc], acc);
        } else {
            acc = Wv[r * HD + (c - 2 * HD)];
        }
        g_Wcat[r * NCAT + c] = acc;
    } else if (c < HD) {
        for (int rr = 0; rr < 3; rr++) {
            float acc = 0.f;
            for (int j = 0; j < HD; j++) acc = fmaf(P2[rr * HD + j], A1[j * HD + c], acc);
            g_P2A1[rr * HD + c] = acc;
        }
        float acc = b1[c];
        for (int j = 0; j < HD; j++) acc = fmaf(bp2[j], A1[j * HD + c], acc);
        g_c1[c] = acc;
    }
}

// ---------------- tiled fp32 GEMM ------------------------------------------
// C[M x 128-per-ytile] = A[M x KD] @ W[KD x N] (+bias). 256 threads, 8 warps.
// Tile: 64 rows x 128 cols, K chunked by 32.
// Thread micro-tile: 4 rows x 8 cols (32 FMA / 6 LDS per k-step).
// Warp w covers rows w*8 + rg*4 + r (rg = lane>>4), cols (lane&15)*8 + q.
// As padded to stride 36: rows 4 apart -> bank +16 (conflict-free), rows
// 144B apart (float4-aligned).
template <int KD, int LDW, int LDC, bool HASBIAS>
__global__ void __launch_bounds__(256) gemm_kernel(const float* __restrict__ A,
                                                   const float* __restrict__ W,
                                                   const float* __restrict__ bias,
                                                   float* __restrict__ C) {
    __shared__ float As[64][36];    // 64 rows x 32 k (+4 pad)
    __shared__ float Bs[32][HD];    // 32 k x 128 cols

    const int tid  = threadIdx.x;
    const int w    = tid >> 5;
    const int lane = tid & 31;
    const int cg   = lane & 15;     // column group (8 cols)
    const int rg   = lane >> 4;     // row group (0/1)
    const int row0 = blockIdx.x * 64;
    const int col0 = blockIdx.y * HD;
    const int rowb = w * 8 + rg * 4;

    float acc[4][8];
#pragma unroll
    for (int r = 0; r < 4; r++)
#pragma unroll
        for (int q = 0; q < 8; q++) acc[r][q] = 0.f;

#pragma unroll 1
    for (int kk = 0; kk < KD; kk += 32) {
        if (kk) __syncthreads();
        // As: 64 rows x 32 floats = 512 float4 items (2 iters)
#pragma unroll
        for (int i = tid; i < 64 * 8; i += 256) {
            int p = i >> 3, q = i & 7;
            *(float4*)&As[p][q * 4] =
                *(const float4*)(A + (size_t)(row0 + p) * KD + kk + q * 4);
        }
        // Bs: 32 rows x 128 floats = 1024 float4 items (4 iters)
#pragma unroll
        for (int i = tid; i < 32 * 32; i += 256) {
            int j = i >> 5, q = i & 31;
            *(float4*)&Bs[j][q * 4] =
                *(const float4*)(W + (size_t)(kk + j) * LDW + col0 + q * 4);
        }
        __syncthreads();

#pragma unroll
        for (int j = 0; j < 32; j++) {
            float4 b0 = *(float4*)&Bs[j][cg * 8];
            float4 b1 = *(float4*)&Bs[j][cg * 8 + 4];
            float bb[8] = {b0.x, b0.y, b0.z, b0.w, b1.x, b1.y, b1.z, b1.w};
            float a[4];
#pragma unroll
            for (int r = 0; r < 4; r++) a[r] = As[rowb + r][j];
#pragma unroll
            for (int r = 0; r < 4; r++)
#pragma unroll
                for (int q = 0; q < 8; q++) acc[r][q] = fmaf(a[r], bb[q], acc[r][q]);
        }
    }

#pragma unroll
    for (int r = 0; r < 4; r++) {
        float* crow = C + (size_t)(row0 + rowb + r) * LDC + col0 + cg * 8;
        float o[8];
#pragma unroll
        for (int q = 0; q < 8; q++) {
            o[q] = acc[r][q];
            if (HASBIAS) o[q] += bias[col0 + cg * 8 + q];
        }
        *(float4*)(crow)     = make_float4(o[0], o[1], o[2], o[3]);
        *(float4*)(crow + 4) = make_float4(o[4], o[5], o[6], o[7]);
    }
}

// ---------------- fused attention kernel: one warp per point ----------------
// lane owns channels c_i = lane*4 + i (contiguous -> float4 gathers).
// head(lane) = lane>>3 (all 4 channels of a lane share one head).
__global__ void __launch_bounds__(128) attn_kernel(const float* __restrict__ xyzs,
                                                   const int* __restrict__ kg,
                                                   const float* __restrict__ A2,
                                                   const float* __restrict__ P1,
                                                   const float* __restrict__ bp1,
                                                   const float* __restrict__ P2,
                                                   const float* __restrict__ bp2) {
    const unsigned FULL = 0xffffffffu;
    const int warp = threadIdx.x >> 5;
    const int lane = threadIdx.x & 31;
    const int pt   = blockIdx.x * 4 + warp;
    const int bN   = pt & ~(NN - 1);
    const int c0   = lane * 4;

    float hbase[4], p2a1c[3][4], A2c[4][4];
    {
        float4 qa = *(const float4*)(g_QKV + (size_t)pt * NCAT + c0);
        float4 c1 = *(const float4*)(g_c1 + c0);
        hbase[0] = qa.x + c1.x; hbase[1] = qa.y + c1.y;
        hbase[2] = qa.z + c1.z; hbase[3] = qa.w + c1.w;
#pragma unroll
        for (int r = 0; r < 3; r++) {
            float4 v = *(const float4*)(g_P2A1 + r * HD + c0);
            p2a1c[r][0] = v.x; p2a1c[r][1] = v.y; p2a1c[r][2] = v.z; p2a1c[r][3] = v.w;
        }
#pragma unroll
        for (int i = 0; i < 4; i++) {
            float4 a2v = *(const float4*)(A2 + (c0 + i) * 4);
            A2c[i][0] = a2v.x; A2c[i][1] = a2v.y; A2c[i][2] = a2v.z; A2c[i][3] = a2v.w;
        }
    }
    float P1r[9];
#pragma unroll
    for (int i = 0; i < 9; i++) P1r[i] = P1[i];
    float bp1r[3] = {bp1[0], bp1[1], bp1[2]};
    const float cx = xyzs[(size_t)pt * 3 + 0];
    const float cy = xyzs[(size_t)pt * 3 + 1];
    const float cz = xyzs[(size_t)pt * 3 + 2];

    // lane l holds neighbor index kg[pt][l&15]
    const int idx_l = kg[(size_t)pt * NK + (lane & 15)];

    const bool hi = (lane & 16) != 0;
    const bool b3 = (lane & 8) != 0;

    float lk0 = 0.f, lk1 = 0.f;

    // ---- pass 1: per-neighbor logits ----
#pragma unroll
    for (int k = 0; k < NK; k++) {
        int idx = __shfl_sync(FULL, idx_l, k);
        const float* nx = xyzs + (size_t)(bN + idx) * 3;
        float rx = cx - nx[0], ry = cy - nx[1], rz = cz - nx[2];
        float t0 = fmaxf(fmaf(rx, P1r[0], fmaf(ry, P1r[3], fmaf(rz, P1r[6], bp1r[0]))), 0.f);
        float t1 = fmaxf(fmaf(rx, P1r[1], fmaf(ry, P1r[4], fmaf(rz, P1r[7], bp1r[1]))), 0.f);
        float t2 = fmaxf(fmaf(rx, P1r[2], fmaf(ry, P1r[5], fmaf(rz, P1r[8], bp1r[2]))), 0.f);
        float4 ka = *(const float4*)(g_QKV + (size_t)(bN + idx) * NCAT + HD + c0);
        float kav[4] = {ka.x, ka.y, ka.z, ka.w};
        float p0 = 0.f, p1 = 0.f, p2 = 0.f, p3 = 0.f;
#pragma unroll
        for (int i = 0; i < 4; i++) {
            float h = hbase[i] - kav[i];
            h = fmaf(t0, p2a1c[0][i], h);
            h = fmaf(t1, p2a1c[1][i], h);
            h = fmaf(t2, p2a1c[2][i], h);
            float r = fmaxf(h, 0.f);
            p0 = fmaf(r, A2c[i][0], p0);
            p1 = fmaf(r, A2c[i][1], p1);
            p2 = fmaf(r, A2c[i][2], p2);
            p3 = fmaf(r, A2c[i][3], p3);
        }
        // split-head reduction: 6 shuffles total
        float sa = hi ? p0 : p2;
        float sb = hi ? p1 : p3;
        float ra = __shfl_xor_sync(FULL, sa, 16);
        float rb = __shfl_xor_sync(FULL, sb, 16);
        float u0 = (hi ? p2 : p0) + ra;
        float u1 = (hi ? p3 : p1) + rb;
        float sc = b3 ? u0 : u1;
        float rc = __shfl_xor_sync(FULL, sc, 8);
        float ww = (b3 ? u1 : u0) + rc;
        ww += __shfl_xor_sync(FULL, ww, 4);
        ww += __shfl_xor_sync(FULL, ww, 2);
        ww += __shfl_xor_sync(FULL, ww, 1);
        // logit(h,k) lands at lane 8h + (k&7); h = lane>>3
        if ((lane & 7) == (k & 7)) {
            if (k < 8) lk0 = ww; else lk1 = ww;
        }
    }

    // ---- softmax: head h in 8-lane group [8h, 8h+7], 2 logits/lane ----
    float mx = fmaxf(lk0, lk1);
    mx = fmaxf(mx, __shfl_xor_sync(FULL, mx, 4));
    mx = fmaxf(mx, __shfl_xor_sync(FULL, mx, 2));
    mx = fmaxf(mx, __shfl_xor_sync(FULL, mx, 1));
    float e0 = __expf(lk0 - mx), e1 = __expf(lk1 - mx);
    float s = e0 + e1;
    s += __shfl_xor_sync(FULL, s, 4);
    s += __shfl_xor_sync(FULL, s, 2);
    s += __shfl_xor_sync(FULL, s, 1);
    float inv = __fdividef(1.f, s);
    float a0 = e0 * inv, a1 = e1 * inv;   // attn(h=lane>>3, k=(lane&7)[+8])

    // per-lane constants for pass 2
    float p2c[3][4], bp2c[4];
#pragma unroll
    for (int r = 0; r < 3; r++) {
        float4 v = *(const float4*)(P2 + r * HD + c0);
        p2c[r][0] = v.x; p2c[r][1] = v.y; p2c[r][2] = v.z; p2c[r][3] = v.w;
    }
    {
        float4 v = *(const float4*)(bp2 + c0);
        bp2c[0] = v.x; bp2c[1] = v.y; bp2c[2] = v.z; bp2c[3] = v.w;
    }

    const int hsrc = lane & 24;   // 8 * head(lane)

    // ---- pass 2: weighted reduce over neighbors ----
    float accv[4] = {0.f, 0.f, 0.f, 0.f};
#pragma unroll
    for (int k = 0; k < NK; k++) {
        float asel = (k < 8) ? a0 : a1;
        float aw = __shfl_sync(FULL, asel, hsrc | (k & 7));  // one shfl: same head for all 4 ch
        int idx = __shfl_sync(FULL, idx_l, k);
        const float* nx = xyzs + (size_t)(bN + idx) * 3;
        float rx = cx - nx[0], ry = cy - nx[1], rz = cz - nx[2];
        float t0 = fmaxf(fmaf(rx, P1r[0], fmaf(ry, P1r[3], fmaf(rz, P1r[6], bp1r[0]))), 0.f);
        float t1 = fmaxf(fmaf(rx, P1r[1], fmaf(ry, P1r[4], fmaf(rz, P1r[7], bp1r[1]))), 0.f);
        float t2 = fmaxf(fmaf(rx, P1r[2], fmaf(ry, P1r[5], fmaf(rz, P1r[8], bp1r[2]))), 0.f);
        float4 vv = *(const float4*)(g_QKV + (size_t)(bN + idx) * NCAT + 2 * HD + c0);
        float vvv[4] = {vv.x, vv.y, vv.z, vv.w};
#pragma unroll
        for (int i = 0; i < 4; i++) {
            float pe = fmaf(t0, p2c[0][i], fmaf(t1, p2c[1][i], fmaf(t2, p2c[2][i], bp2c[i])));
            accv[i] = fmaf(aw, vvv[i] + pe, accv[i]);
        }
    }
    *(float4*)(g_fused + (size_t)pt * HD + c0) =
        make_float4(accv[0], accv[1], accv[2], accv[3]);
}

// ---------------- launch ----------------------------------------------------
extern "C" void kernel_launch(void* const* d_in, const int* in_sizes, int n_in,
                              void* d_out, int out_size) {
    const float* xyzs     = (const float*)d_in[0];
    const float* features = (const float*)d_in[1];
    const int*   kg       = (const int*)d_in[2];
    const float* Wk   = (const float*)d_in[3];
    const float* Wv   = (const float*)d_in[4];
    const float* Wq   = (const float*)d_in[5];
    const float* A1   = (const float*)d_in[6];
    const float* b1   = (const float*)d_in[7];
    const float* A2   = (const float*)d_in[8];
    const float* P1   = (const float*)d_in[10];
    const float* bp1  = (const float*)d_in[11];
    const float* P2   = (const float*)d_in[12];
    const float* bp2  = (const float*)d_in[13];
    const float* Wout = (const float*)d_in[14];
    const float* bout = (const float*)d_in[15];
    float* out = (float*)d_out;

    float *pWcat, *pQKV, *pFused;
    cudaGetSymbolAddress((void**)&pWcat,  g_Wcat);
    cudaGetSymbolAddress((void**)&pQKV,   g_QKV);
    cudaGetSymbolAddress((void**)&pFused, g_fused);

    setup_kernel<<<CIN + 1, NCAT>>>(Wq, Wk, Wv, A1, P2, b1, bp2);

    // QA|KA|V in one GEMM: [16384 x 64] @ [64 x 384]
    gemm_kernel<CIN, NCAT, NCAT, false>
        <<<dim3(NPTS / 64, 3), 256>>>(features, pWcat, nullptr, pQKV);

    attn_kernel<<<NPTS / 4, 128>>>(xyzs, kg, A2, P1, bp1, P2, bp2);

    // out = fused @ Wout + bout : [16384 x 128] @ [128 x 128]
    gemm_kernel<HD, HD, HD, true>
        <<<dim3(NPTS / 64, 1), 256>>>(pFused, Wout, bout, out);
}

// round 4
// speedup vs baseline: 1.1726x; 1.1726x over previous
#include <cuda_runtime.h>

#define NB   2
#define NN   8192
#define NK   16
#define NH   4
#define ND   32
#define HD   128
#define CIN  64
#define COUT 128
#define NPTS (NB * NN)   // 16384
#define NCAT 384         // QA|KA|V concatenated

// ---------------- scratch (device globals; no allocations allowed) ----------
__device__ float g_Wcat[CIN * NCAT];   // [WqA1 | WkA1 | Wv]
__device__ float g_P2A1[3 * HD];
__device__ float g_c1[HD];
__device__ float g_QKV[NPTS * NCAT];   // per-point [QA(128) | KA(128) | V(128)]
__device__ float g_fused[NPTS * HD];

// ---------------- weight folding -------------------------------------------
__global__ void setup_kernel(const float* __restrict__ Wq, const float* __restrict__ Wk,
                             const float* __restrict__ Wv, const float* __restrict__ A1,
                             const float* __restrict__ P2, const float* __restrict__ b1,
                             const float* __restrict__ bp2) {
    int c = threadIdx.x;          // 0..383
    int r = blockIdx.x;
    if (r < CIN) {
        float acc;
        if (c < HD) {
            acc = 0.f;
            for (int j = 0; j < HD; j++) acc = fmaf(Wq[r * HD + j], A1[j * HD + c], acc);
        } else if (c < 2 * HD) {
            int cc = c - HD;
            acc = 0.f;
            for (int j = 0; j < HD; j++) acc = fmaf(Wk[r * HD + j], A1[j * HD + cc], acc);
        } else {
            acc = Wv[r * HD + (c - 2 * HD)];
        }
        g_Wcat[r * NCAT + c] = acc;
    } else if (c < HD) {
        for (int rr = 0; rr < 3; rr++) {
            float acc = 0.f;
            for (int j = 0; j < HD; j++) acc = fmaf(P2[rr * HD + j], A1[j * HD + c], acc);
            g_P2A1[rr * HD + c] = acc;
        }
        float acc = b1[c];
        for (int j = 0; j < HD; j++) acc = fmaf(bp2[j], A1[j * HD + c], acc);
        g_c1[c] = acc;
    }
}

// ---------------- tiled fp32 GEMM ------------------------------------------
// C tile = 32 rows x 64 cols per block (128 threads, 4 warps).
// Micro-tile 4x4: 16 FMA : (1 LDS.128 + 4 broadcast LDS.32) per k-step.
// Warp w owns rows w*8 + (lane>>4)*4 + r; lane&15 selects a 4-col group.
// As padded to stride 68: rows 4 apart -> bank +16 (conflict-free).
template <int KD, int LDW, int LDC, bool HASBIAS>
__global__ void __launch_bounds__(128) gemm_kernel(const float* __restrict__ A,
                                                   const float* __restrict__ W,
                                                   const float* __restrict__ bias,
                                                   float* __restrict__ C) {
    __shared__ float As[32][68];    // 32 rows x 64 k (+4 pad)
    __shared__ float Bs[64][64];    // 64 k x 64 cols

    const int tid  = threadIdx.x;
    const int w    = tid >> 5;
    const int lane = tid & 31;
    const int cg   = lane & 15;     // column group (4 cols)
    const int rg   = lane >> 4;     // row group (0/1)
    const int row0 = blockIdx.x * 32;
    const int col0 = blockIdx.y * 64;
    const int rowb = w * 8 + rg * 4;

    float acc[4][4];
#pragma unroll
    for (int r = 0; r < 4; r++)
#pragma unroll
        for (int q = 0; q < 4; q++) acc[r][q] = 0.f;

#pragma unroll 1
    for (int kk = 0; kk < KD; kk += 64) {
        if (kk) __syncthreads();
        // As: 32 rows x 64 floats = 512 float4 (4 iters)
#pragma unroll
        for (int i = tid; i < 32 * 16; i += 128) {
            int p = i >> 4, q = i & 15;
            *(float4*)&As[p][q * 4] =
                *(const float4*)(A + (size_t)(row0 + p) * KD + kk + q * 4);
        }
        // Bs: 64 rows x 64 floats = 1024 float4 (8 iters)
#pragma unroll
        for (int i = tid; i < 64 * 16; i += 128) {
            int j = i >> 4, q = i & 15;
            *(float4*)&Bs[j][q * 4] =
                *(const float4*)(W + (size_t)(kk + j) * LDW + col0 + q * 4);
        }
        __syncthreads();

#pragma unroll 16
        for (int j = 0; j < 64; j++) {
            float4 b = *(float4*)&Bs[j][cg * 4];
            float bb[4] = {b.x, b.y, b.z, b.w};
            float a[4];
#pragma unroll
            for (int r = 0; r < 4; r++) a[r] = As[rowb + r][j];
#pragma unroll
            for (int r = 0; r < 4; r++)
#pragma unroll
                for (int q = 0; q < 4; q++) acc[r][q] = fmaf(a[r], bb[q], acc[r][q]);
        }
    }

#pragma unroll
    for (int r = 0; r < 4; r++) {
        float* crow = C + (size_t)(row0 + rowb + r) * LDC + col0 + cg * 4;
        float o[4];
#pragma unroll
        for (int q = 0; q < 4; q++) {
            o[q] = acc[r][q];
            if (HASBIAS) o[q] += bias[col0 + cg * 4 + q];
        }
        *(float4*)crow = make_float4(o[0], o[1], o[2], o[3]);
    }
}

// ---------------- fused attention kernel: one warp per point ----------------
// lane owns channels c_i = lane*4 + i (contiguous -> float4 gathers).
// head(lane) = lane>>3 (all 4 channels of a lane share one head).
__global__ void __launch_bounds__(128) attn_kernel(const float* __restrict__ xyzs,
                                                   const int* __restrict__ kg,
                                                   const float* __restrict__ A2,
                                                   const float* __restrict__ P1,
                                                   const float* __restrict__ bp1,
                                                   const float* __restrict__ P2,
                                                   const float* __restrict__ bp2) {
    const unsigned FULL = 0xffffffffu;
    const int warp = threadIdx.x >> 5;
    const int lane = threadIdx.x & 31;
    const int pt   = blockIdx.x * 4 + warp;
    const int bN   = pt & ~(NN - 1);
    const int c0   = lane * 4;

    float hbase[4], p2a1c[3][4], A2c[4][4];
    {
        float4 qa = *(const float4*)(g_QKV + (size_t)pt * NCAT + c0);
        float4 c1 = *(const float4*)(g_c1 + c0);
        hbase[0] = qa.x + c1.x; hbase[1] = qa.y + c1.y;
        hbase[2] = qa.z + c1.z; hbase[3] = qa.w + c1.w;
#pragma unroll
        for (int r = 0; r < 3; r++) {
            float4 v = *(const float4*)(g_P2A1 + r * HD + c0);
            p2a1c[r][0] = v.x; p2a1c[r][1] = v.y; p2a1c[r][2] = v.z; p2a1c[r][3] = v.w;
        }
#pragma unroll
        for (int i = 0; i < 4; i++) {
            float4 a2v = *(const float4*)(A2 + (c0 + i) * 4);
            A2c[i][0] = a2v.x; A2c[i][1] = a2v.y; A2c[i][2] = a2v.z; A2c[i][3] = a2v.w;
        }
    }
    float P1r[9];
#pragma unroll
    for (int i = 0; i < 9; i++) P1r[i] = P1[i];
    float bp1r[3] = {bp1[0], bp1[1], bp1[2]};
    const float cx = xyzs[(size_t)pt * 3 + 0];
    const float cy = xyzs[(size_t)pt * 3 + 1];
    const float cz = xyzs[(size_t)pt * 3 + 2];

    // lane l holds neighbor index kg[pt][l&15]
    const int idx_l = kg[(size_t)pt * NK + (lane & 15)];

    const bool hi = (lane & 16) != 0;
    const bool b3 = (lane & 8) != 0;

    float lk0 = 0.f, lk1 = 0.f;

    // ---- pass 1: per-neighbor logits ----
#pragma unroll
    for (int k = 0; k < NK; k++) {
        int idx = __shfl_sync(FULL, idx_l, k);
        const float* nx = xyzs + (size_t)(bN + idx) * 3;
        float rx = cx - nx[0], ry = cy - nx[1], rz = cz - nx[2];
        float t0 = fmaxf(fmaf(rx, P1r[0], fmaf(ry, P1r[3], fmaf(rz, P1r[6], bp1r[0]))), 0.f);
        float t1 = fmaxf(fmaf(rx, P1r[1], fmaf(ry, P1r[4], fmaf(rz, P1r[7], bp1r[1]))), 0.f);
        float t2 = fmaxf(fmaf(rx, P1r[2], fmaf(ry, P1r[5], fmaf(rz, P1r[8], bp1r[2]))), 0.f);
        float4 ka = *(const float4*)(g_QKV + (size_t)(bN + idx) * NCAT + HD + c0);
        float kav[4] = {ka.x, ka.y, ka.z, ka.w};
        float p0 = 0.f, p1 = 0.f, p2 = 0.f, p3 = 0.f;
#pragma unroll
        for (int i = 0; i < 4; i++) {
            float h = hbase[i] - kav[i];
            h = fmaf(t0, p2a1c[0][i], h);
            h = fmaf(t1, p2a1c[1][i], h);
            h = fmaf(t2, p2a1c[2][i], h);
            float r = fmaxf(h, 0.f);
            p0 = fmaf(r, A2c[i][0], p0);
            p1 = fmaf(r, A2c[i][1], p1);
            p2 = fmaf(r, A2c[i][2], p2);
            p3 = fmaf(r, A2c[i][3], p3);
        }
        // split-head reduction: 6 shuffles total
        float sa = hi ? p0 : p2;
        float sb = hi ? p1 : p3;
        float ra = __shfl_xor_sync(FULL, sa, 16);
        float rb = __shfl_xor_sync(FULL, sb, 16);
        float u0 = (hi ? p2 : p0) + ra;
        float u1 = (hi ? p3 : p1) + rb;
        float sc = b3 ? u0 : u1;
        float rc = __shfl_xor_sync(FULL, sc, 8);
        float ww = (b3 ? u1 : u0) + rc;
        ww += __shfl_xor_sync(FULL, ww, 4);
        ww += __shfl_xor_sync(FULL, ww, 2);
        ww += __shfl_xor_sync(FULL, ww, 1);
        // logit(h,k) lands at lane 8h + (k&7); h = lane>>3
        if ((lane & 7) == (k & 7)) {
            if (k < 8) lk0 = ww; else lk1 = ww;
        }
    }

    // ---- softmax: head h in 8-lane group [8h, 8h+7], 2 logits/lane ----
    float mx = fmaxf(lk0, lk1);
    mx = fmaxf(mx, __shfl_xor_sync(FULL, mx, 4));
    mx = fmaxf(mx, __shfl_xor_sync(FULL, mx, 2));
    mx = fmaxf(mx, __shfl_xor_sync(FULL, mx, 1));
    float e0 = __expf(lk0 - mx), e1 = __expf(lk1 - mx);
    float s = e0 + e1;
    s += __shfl_xor_sync(FULL, s, 4);
    s += __shfl_xor_sync(FULL, s, 2);
    s += __shfl_xor_sync(FULL, s, 1);
    float inv = __fdividef(1.f, s);
    float a0 = e0 * inv, a1 = e1 * inv;   // attn(h=lane>>3, k=(lane&7)[+8])

    // per-lane constants for pass 2
    float p2c[3][4], bp2c[4];
#pragma unroll
    for (int r = 0; r < 3; r++) {
        float4 v = *(const float4*)(P2 + r * HD + c0);
        p2c[r][0] = v.x; p2c[r][1] = v.y; p2c[r][2] = v.z; p2c[r][3] = v.w;
    }
    {
        float4 v = *(const float4*)(bp2 + c0);
        bp2c[0] = v.x; bp2c[1] = v.y; bp2c[2] = v.z; bp2c[3] = v.w;
    }

    const int hsrc = lane & 24;   // 8 * head(lane)

    // ---- pass 2: weighted reduce over neighbors ----
    float accv[4] = {0.f, 0.f, 0.f, 0.f};
#pragma unroll
    for (int k = 0; k < NK; k++) {
        float asel = (k < 8) ? a0 : a1;
        float aw = __shfl_sync(FULL, asel, hsrc | (k & 7));  // one shfl for all 4 channels
        int idx = __shfl_sync(FULL, idx_l, k);
        const float* nx = xyzs + (size_t)(bN + idx) * 3;
        float rx = cx - nx[0], ry = cy - nx[1], rz = cz - nx[2];
        float t0 = fmaxf(fmaf(rx, P1r[0], fmaf(ry, P1r[3], fmaf(rz, P1r[6], bp1r[0]))), 0.f);
        float t1 = fmaxf(fmaf(rx, P1r[1], fmaf(ry, P1r[4], fmaf(rz, P1r[7], bp1r[1]))), 0.f);
        float t2 = fmaxf(fmaf(rx, P1r[2], fmaf(ry, P1r[5], fmaf(rz, P1r[8], bp1r[2]))), 0.f);
        float4 vv = *(const float4*)(g_QKV + (size_t)(bN + idx) * NCAT + 2 * HD + c0);
        float vvv[4] = {vv.x, vv.y, vv.z, vv.w};
#pragma unroll
        for (int i = 0; i < 4; i++) {
            float pe = fmaf(t0, p2c[0][i], fmaf(t1, p2c[1][i], fmaf(t2, p2c[2][i], bp2c[i])));
            accv[i] = fmaf(aw, vvv[i] + pe, accv[i]);
        }
    }
    *(float4*)(g_fused + (size_t)pt * HD + c0) =
        make_float4(accv[0], accv[1], accv[2], accv[3]);
}

// ---------------- launch ----------------------------------------------------
extern "C" void kernel_launch(void* const* d_in, const int* in_sizes, int n_in,
                              void* d_out, int out_size) {
    const float* xyzs     = (const float*)d_in[0];
    const float* features = (const float*)d_in[1];
    const int*   kg       = (const int*)d_in[2];
    const float* Wk   = (const float*)d_in[3];
    const float* Wv   = (const float*)d_in[4];
    const float* Wq   = (const float*)d_in[5];
    const float* A1   = (const float*)d_in[6];
    const float* b1   = (const float*)d_in[7];
    const float* A2   = (const float*)d_in[8];
    const float* P1   = (const float*)d_in[10];
    const float* bp1  = (const float*)d_in[11];
    const float* P2   = (const float*)d_in[12];
    const float* bp2  = (const float*)d_in[13];
    const float* Wout = (const float*)d_in[14];
    const float* bout = (const float*)d_in[15];
    float* out = (float*)d_out;

    float *pWcat, *pQKV, *pFused;
    cudaGetSymbolAddress((void**)&pWcat,  g_Wcat);
    cudaGetSymbolAddress((void**)&pQKV,   g_QKV);
    cudaGetSymbolAddress((void**)&pFused, g_fused);

    setup_kernel<<<CIN + 1, NCAT>>>(Wq, Wk, Wv, A1, P2, b1, bp2);

    // QA|KA|V in one GEMM: [16384 x 64] @ [64 x 384] -> 512 x 6 = 3072 blocks
    gemm_kernel<CIN, NCAT, NCAT, false>
        <<<dim3(NPTS / 32, NCAT / 64), 128>>>(features, pWcat, nullptr, pQKV);

    attn_kernel<<<NPTS / 4, 128>>>(xyzs, kg, A2, P1, bp1, P2, bp2);

    // out = fused @ Wout + bout : [16384 x 128] @ [128 x 128] -> 512 x 2 = 1024 blocks
    gemm_kernel<HD, HD, HD, true>
        <<<dim3(NPTS / 32, HD / 64), 128>>>(pFused, Wout, bout, out);
}

// round 6
// speedup vs baseline: 1.3910x; 1.1862x over previous
#include <cuda_runtime.h>
#include <cuda_bf16.h>
#include <cstdint>

#define NB   2
#define NN   8192
#define NK   16
#define HD   128
#define CIN  64
#define COUT 128
#define NPTS (NB * NN)   // 16384
#define NCAT 384         // QA|KA|V concatenated

// ---------------- helpers ----------------------------------------------------
__device__ __forceinline__ uint32_t smem_to_u32(const void* p) {
    uint32_t a;
    asm("{ .reg .u64 t; cvta.to.shared.u64 t, %1; cvt.u32.u64 %0, t; }"
        : "=r"(a) : "l"(p));
    return a;
}
#define LDSM_X4(r0, r1, r2, r3, addr) \
    asm volatile("ldmatrix.sync.aligned.m8n8.x4.shared.b16 {%0,%1,%2,%3}, [%4];" \
                 : "=r"(r0), "=r"(r1), "=r"(r2), "=r"(r3) : "r"(addr))
#define MMA_BF16(c, a, b0, b1) \
    asm volatile("mma.sync.aligned.m16n8k16.row.col.f32.bf16.bf16.f32 " \
                 "{%0,%1,%2,%3}, {%4,%5,%6,%7}, {%8,%9}, {%0,%1,%2,%3};" \
                 : "+f"((c)[0]), "+f"((c)[1]), "+f"((c)[2]), "+f"((c)[3]) \
                 : "r"((a)[0]), "r"((a)[1]), "r"((a)[2]), "r"((a)[3]), \
                   "r"(b0), "r"(b1))
#define SWZ(b) ((b) ^ (((b) >> 3) & 0x70))

// ---------------- scratch globals --------------------------------------------
__device__ float g_Wcat[CIN * NCAT];                       // folded fp32 [k][n]
__device__ float g_P2A1[3 * HD];
__device__ float g_c1[HD];
__device__ __align__(16) float g_QKV[NPTS * NCAT];
__device__ __align__(16) __nv_bfloat16 g_featP[NPTS * 192];    // [Ah|Al|Ah]
__device__ __align__(16) __nv_bfloat16 g_WcatP[NCAT * 192];    // [n][Bh|Bh|Bl]
__device__ __align__(16) __nv_bfloat16 g_WoutP[HD * 384];      // [n][Bh|Bh|Bl]
__device__ __align__(16) __nv_bfloat16 g_fusedP[NPTS * 384];   // [Fh|Fl|Fh]

// ---------------- weight folding (fp32) --------------------------------------
__global__ void setup_kernel(const float* __restrict__ Wq, const float* __restrict__ Wk,
                             const float* __restrict__ Wv, const float* __restrict__ A1,
                             const float* __restrict__ P2, const float* __restrict__ b1,
                             const float* __restrict__ bp2) {
    int c = threadIdx.x;          // 0..383
    int r = blockIdx.x;
    if (r < CIN) {
        float acc;
        if (c < HD) {
            acc = 0.f;
            for (int j = 0; j < HD; j++) acc = fmaf(Wq[r * HD + j], A1[j * HD + c], acc);
        } else if (c < 2 * HD) {
            int cc = c - HD;
            acc = 0.f;
            for (int j = 0; j < HD; j++) acc = fmaf(Wk[r * HD + j], A1[j * HD + cc], acc);
        } else {
            acc = Wv[r * HD + (c - 2 * HD)];
        }
        g_Wcat[r * NCAT + c] = acc;
    } else if (c < HD) {
        for (int rr = 0; rr < 3; rr++) {
            float acc = 0.f;
            for (int j = 0; j < HD; j++) acc = fmaf(P2[rr * HD + j], A1[j * HD + c], acc);
            g_P2A1[rr * HD + c] = acc;
        }
        float acc = b1[c];
        for (int j = 0; j < HD; j++) acc = fmaf(bp2[j], A1[j * HD + c], acc);
        g_c1[c] = acc;
    }
}

// transpose + bf16 hi/lo K-pack of weights.
// blocks 0..383: Wcat col n -> g_WcatP row n. blocks 384..511: Wout col n.
__global__ void setup2_kernel(const float* __restrict__ Wout) {
    int b = blockIdx.x, t = threadIdx.x;
    if (b < NCAT) {
        if (t < CIN) {
            float w = g_Wcat[t * NCAT + b];
            __nv_bfloat16 h = __float2bfloat16_rn(w);
            __nv_bfloat16 l = __float2bfloat16_rn(w - __bfloat162float(h));
            g_WcatP[b * 192 + t]       = h;
            g_WcatP[b * 192 + 64 + t]  = h;
            g_WcatP[b * 192 + 128 + t] = l;
        }
    } else {
        int n = b - NCAT;
        float w = Wout[t * HD + n];
        __nv_bfloat16 h = __float2bfloat16_rn(w);
        __nv_bfloat16 l = __float2bfloat16_rn(w - __bfloat162float(h));
        g_WoutP[n * 384 + t]       = h;
        g_WoutP[n * 384 + 128 + t] = h;
        g_WoutP[n * 384 + 256 + t] = l;
    }
}

// features -> bf16 hi/lo K-packed [Ah|Al|Ah]
__global__ void convert_feat_kernel(const float* __restrict__ feat) {
    int e = blockIdx.x * 256 + threadIdx.x;     // e < NPTS*CIN/4
    float4 v = ((const float4*)feat)[e];
    int pt = e >> 4, k = (e & 15) * 4;
    __nv_bfloat16 h0 = __float2bfloat16_rn(v.x), h1 = __float2bfloat16_rn(v.y);
    __nv_bfloat16 h2 = __float2bfloat16_rn(v.z), h3 = __float2bfloat16_rn(v.w);
    __nv_bfloat16 l0 = __float2bfloat16_rn(v.x - __bfloat162float(h0));
    __nv_bfloat16 l1 = __float2bfloat16_rn(v.y - __bfloat162float(h1));
    __nv_bfloat16 l2 = __float2bfloat16_rn(v.z - __bfloat162float(h2));
    __nv_bfloat16 l3 = __float2bfloat16_rn(v.w - __bfloat162float(h3));
    __nv_bfloat162 hA = __halves2bfloat162(h0, h1), hB = __halves2bfloat162(h2, h3);
    __nv_bfloat162 lA = __halves2bfloat162(l0, l1), lB = __halves2bfloat162(l2, l3);
    __nv_bfloat162* base = (__nv_bfloat162*)(g_featP + (size_t)pt * 192 + k);
    base[0] = hA; base[1] = hB;
    base[32] = lA; base[33] = lB;          // +64 elems
    base[64] = hA; base[65] = hB;          // +128 elems
}

// ---------------- mma.sync GEMM ----------------------------------------------
// C[M x N] = A'[M x KTOT](bf16) @ B'[N x KTOT](bf16, row=n) + bias, fp32 accum.
// CTA: 128 thr (4 warps), tile 64(M) x 64(N), K chunked by 64.
// Warp: 32x32 -> 2 m16-tiles x 4 n8-tiles, m16n8k16 bf16 mma.
template <int KTOT, int LDA, int LDB, int LDC, bool HASBIAS>
__global__ void __launch_bounds__(128) mma_gemm_kernel(const __nv_bfloat16* __restrict__ A,
                                                       const __nv_bfloat16* __restrict__ B,
                                                       const float* __restrict__ bias,
                                                       float* __restrict__ C) {
    __shared__ __align__(16) char sA[64 * 128];   // 64 rows x 64 bf16 (swizzled)
    __shared__ __align__(16) char sB[64 * 128];

    const int tid = threadIdx.x, wid = tid >> 5, lane = tid & 31;
    const int row0 = blockIdx.x * 64, col0 = blockIdx.y * 64;
    const int wm = (wid & 1) * 32, wn = (wid >> 1) * 32;
    const uint32_t sAb = smem_to_u32(sA), sBb = smem_to_u32(sB);

    float c[2][4][4];
#pragma unroll
    for (int mt = 0; mt < 2; mt++)
#pragma unroll
        for (int nt = 0; nt < 4; nt++)
#pragma unroll
            for (int q = 0; q < 4; q++) c[mt][nt][q] = 0.f;

    // lane-constant pieces of ldmatrix addresses
    const uint32_t lrow = lane & 15;            // row within 16-row group
    const uint32_t lcb  = (lane >> 4) * 16;     // 0 or 16 bytes (k 8-group)

#pragma unroll
    for (int ch = 0; ch < KTOT / 64; ch++) {
        if (ch) __syncthreads();
#pragma unroll
        for (int i = tid; i < 512; i += 128) {
            int r = i >> 3, c16 = i & 7;
            uint32_t b = SWZ((uint32_t)(r * 128 + c16 * 16));
            *(uint4*)(sA + b) = *(const uint4*)(A + (size_t)(row0 + r) * LDA + ch * 64 + c16 * 8);
        }
#pragma unroll
        for (int i = tid; i < 512; i += 128) {
            int r = i >> 3, c16 = i & 7;
            uint32_t b = SWZ((uint32_t)(r * 128 + c16 * 16));
            *(uint4*)(sB + b) = *(const uint4*)(B + (size_t)(col0 + r) * LDB + ch * 64 + c16 * 8);
        }
        __syncthreads();

#pragma unroll
        for (int k16 = 0; k16 < 4; k16++) {
            uint32_t a[2][4], bf[2][4];
#pragma unroll
            for (int mt = 0; mt < 2; mt++) {
                uint32_t b = SWZ((wm + mt * 16 + lrow) * 128 + k16 * 32 + lcb);
                LDSM_X4(a[mt][0], a[mt][1], a[mt][2], a[mt][3], sAb + b);
            }
#pragma unroll
            for (int np = 0; np < 2; np++) {
                uint32_t b = SWZ((wn + np * 16 + lrow) * 128 + k16 * 32 + lcb);
                LDSM_X4(bf[np][0], bf[np][1], bf[np][2], bf[np][3], sBb + b);
            }
#pragma unroll
            for (int mt = 0; mt < 2; mt++) {
#pragma unroll
                for (int nt = 0; nt < 4; nt++)
                    MMA_BF16(c[mt][nt], a[mt], bf[nt >> 1][nt & 1], bf[nt >> 1][(nt & 1) + 2]);
            }
        }
    }

    // epilogue
#pragma unroll
    for (int mt = 0; mt < 2; mt++) {
        int r = row0 + wm + mt * 16 + (lane >> 2);
#pragma unroll
        for (int nt = 0; nt < 4; nt++) {
            int cc = col0 + wn + nt * 8 + (lane & 3) * 2;
            float bx = 0.f, by = 0.f;
            if (HASBIAS) { bx = bias[cc]; by = bias[cc + 1]; }
            *(float2*)(C + (size_t)r * LDC + cc) =
                make_float2(c[mt][nt][0] + bx, c[mt][nt][1] + by);
            *(float2*)(C + (size_t)(r + 8) * LDC + cc) =
                make_float2(c[mt][nt][2] + bx, c[mt][nt][3] + by);
        }
    }
}

// ---------------- fused attention kernel: one warp per point ----------------
__global__ void __launch_bounds__(128) attn_kernel(const float* __restrict__ xyzs,
                                                   const int* __restrict__ kg,
                                                   const float* __restrict__ A2,
                                                   const float* __restrict__ P1,
                                                   const float* __restrict__ bp1,
                                                   const float* __restrict__ P2,
                                                   const float* __restrict__ bp2) {
    const unsigned FULL = 0xffffffffu;
    const int warp = threadIdx.x >> 5;
    const int lane = threadIdx.x & 31;
    const int pt   = blockIdx.x * 4 + warp;
    const int bN   = pt & ~(NN - 1);
    const int c0   = lane * 4;

    float hbase[4], p2a1c[3][4], A2c[4][4];
    {
        float4 qa = *(const float4*)(g_QKV + (size_t)pt * NCAT + c0);
        float4 c1 = *(const float4*)(g_c1 + c0);
        hbase[0] = qa.x + c1.x; hbase[1] = qa.y + c1.y;
        hbase[2] = qa.z + c1.z; hbase[3] = qa.w + c1.w;
#pragma unroll
        for (int r = 0; r < 3; r++) {
            float4 v = *(const float4*)(g_P2A1 + r * HD + c0);
            p2a1c[r][0] = v.x; p2a1c[r][1] = v.y; p2a1c[r][2] = v.z; p2a1c[r][3] = v.w;
        }
#pragma unroll
        for (int i = 0; i < 4; i++) {
            float4 a2v = *(const float4*)(A2 + (c0 + i) * 4);
            A2c[i][0] = a2v.x; A2c[i][1] = a2v.y; A2c[i][2] = a2v.z; A2c[i][3] = a2v.w;
        }
    }
    float P1r[9];
#pragma unroll
    for (int i = 0; i < 9; i++) P1r[i] = P1[i];
    float bp1r[3] = {bp1[0], bp1[1], bp1[2]};
    const float cx = xyzs[(size_t)pt * 3 + 0];
    const float cy = xyzs[(size_t)pt * 3 + 1];
    const float cz = xyzs[(size_t)pt * 3 + 2];

    const int idx_l = kg[(size_t)pt * NK + (lane & 15)];

    const bool hi = (lane & 16) != 0;
    const bool b3 = (lane & 8) != 0;

    float lk0 = 0.f, lk1 = 0.f;

#pragma unroll
    for (int k = 0; k < NK; k++) {
        int idx = __shfl_sync(FULL, idx_l, k);
        const float* nx = xyzs + (size_t)(bN + idx) * 3;
        float rx = cx - nx[0], ry = cy - nx[1], rz = cz - nx[2];
        float t0 = fmaxf(fmaf(rx, P1r[0], fmaf(ry, P1r[3], fmaf(rz, P1r[6], bp1r[0]))), 0.f);
        float t1 = fmaxf(fmaf(rx, P1r[1], fmaf(ry, P1r[4], fmaf(rz, P1r[7], bp1r[1]))), 0.f);
        float t2 = fmaxf(fmaf(rx, P1r[2], fmaf(ry, P1r[5], fmaf(rz, P1r[8], bp1r[2]))), 0.f);
        float4 ka = *(const float4*)(g_QKV + (size_t)(bN + idx) * NCAT + HD + c0);
        float kav[4] = {ka.x, ka.y, ka.z, ka.w};
        float p0 = 0.f, p1 = 0.f, p2 = 0.f, p3 = 0.f;
#pragma unroll
        for (int i = 0; i < 4; i++) {
            float h = hbase[i] - kav[i];
            h = fmaf(t0, p2a1c[0][i], h);
            h = fmaf(t1, p2a1c[1][i], h);
            h = fmaf(t2, p2a1c[2][i], h);
            float r = fmaxf(h, 0.f);
            p0 = fmaf(r, A2c[i][0], p0);
            p1 = fmaf(r, A2c[i][1], p1);
            p2 = fmaf(r, A2c[i][2], p2);
            p3 = fmaf(r, A2c[i][3], p3);
        }
        float sa = hi ? p0 : p2;
        float sb = hi ? p1 : p3;
        float ra = __shfl_xor_sync(FULL, sa, 16);
        float rb = __shfl_xor_sync(FULL, sb, 16);
        float u0 = (hi ? p2 : p0) + ra;
        float u1 = (hi ? p3 : p1) + rb;
        float sc = b3 ? u0 : u1;
        float rc = __shfl_xor_sync(FULL, sc, 8);
        float ww = (b3 ? u1 : u0) + rc;
        ww += __shfl_xor_sync(FULL, ww, 4);
        ww += __shfl_xor_sync(FULL, ww, 2);
        ww += __shfl_xor_sync(FULL, ww, 1);
        if ((lane & 7) == (k & 7)) {
            if (k < 8) lk0 = ww; else lk1 = ww;
        }
    }

    float mx = fmaxf(lk0, lk1);
    mx = fmaxf(mx, __shfl_xor_sync(FULL, mx, 4));
    mx = fmaxf(mx, __shfl_xor_sync(FULL, mx, 2));
    mx = fmaxf(mx, __shfl_xor_sync(FULL, mx, 1));
    float e0 = __expf(lk0 - mx), e1 = __expf(lk1 - mx);
    float s = e0 + e1;
    s += __shfl_xor_sync(FULL, s, 4);
    s += __shfl_xor_sync(FULL, s, 2);
    s += __shfl_xor_sync(FULL, s, 1);
    float inv = __fdividef(1.f, s);
    float a0 = e0 * inv, a1 = e1 * inv;

    float p2c[3][4], bp2c[4];
#pragma unroll
    for (int r = 0; r < 3; r++) {
        float4 v = *(const float4*)(P2 + r * HD + c0);
        p2c[r][0] = v.x; p2c[r][1] = v.y; p2c[r][2] = v.z; p2c[r][3] = v.w;
    }
    {
        float4 v = *(const float4*)(bp2 + c0);
        bp2c[0] = v.x; bp2c[1] = v.y; bp2c[2] = v.z; bp2c[3] = v.w;
    }

    const int hsrc = lane & 24;

    float accv[4] = {0.f, 0.f, 0.f, 0.f};
#pragma unroll
    for (int k = 0; k < NK; k++) {
        float asel = (k < 8) ? a0 : a1;
        float aw = __shfl_sync(FULL, asel, hsrc | (k & 7));
        int idx = __shfl_sync(FULL, idx_l, k);
        const float* nx = xyzs + (size_t)(bN + idx) * 3;
        float rx = cx - nx[0], ry = cy - nx[1], rz = cz - nx[2];
        float t0 = fmaxf(fmaf(rx, P1r[0], fmaf(ry, P1r[3], fmaf(rz, P1r[6], bp1r[0]))), 0.f);
        float t1 = fmaxf(fmaf(rx, P1r[1], fmaf(ry, P1r[4], fmaf(rz, P1r[7], bp1r[1]))), 0.f);
        float t2 = fmaxf(fmaf(rx, P1r[2], fmaf(ry, P1r[5], fmaf(rz, P1r[8], bp1r[2]))), 0.f);
        float4 vv = *(const float4*)(g_QKV + (size_t)(bN + idx) * NCAT + 2 * HD + c0);
        float vvv[4] = {vv.x, vv.y, vv.z, vv.w};
#pragma unroll
        for (int i = 0; i < 4; i++) {
            float pe = fmaf(t0, p2c[0][i], fmaf(t1, p2c[1][i], fmaf(t2, p2c[2][i], bp2c[i])));
            accv[i] = fmaf(aw, vvv[i] + pe, accv[i]);
        }
    }
    // write fused K-packed: [Fh | Fl | Fh]
    {
        __nv_bfloat16 h0 = __float2bfloat16_rn(accv[0]);
        __nv_bfloat16 h1 = __float2bfloat16_rn(accv[1]);
        __nv_bfloat16 h2 = __float2bfloat16_rn(accv[2]);
        __nv_bfloat16 h3 = __float2bfloat16_rn(accv[3]);
        __nv_bfloat16 l0 = __float2bfloat16_rn(accv[0] - __bfloat162float(h0));
        __nv_bfloat16 l1 = __float2bfloat16_rn(accv[1] - __bfloat162float(h1));
        __nv_bfloat16 l2 = __float2bfloat16_rn(accv[2] - __bfloat162float(h2));
        __nv_bfloat16 l3 = __float2bfloat16_rn(accv[3] - __bfloat162float(h3));
        __nv_bfloat162 hA = __halves2bfloat162(h0, h1), hB = __halves2bfloat162(h2, h3);
        __nv_bfloat162 lA = __halves2bfloat162(l0, l1), lB = __halves2bfloat162(l2, l3);
        __nv_bfloat162* base = (__nv_bfloat162*)(g_fusedP + (size_t)pt * 384 + c0);
        base[0]  = hA; base[1]  = hB;
        base[64] = lA; base[65] = lB;      // +128 elems
        base[128] = hA; base[129] = hB;    // +256 elems
    }
}

// ======================= launch =============================================
extern "C" void kernel_launch(void* const* d_in, const int* in_sizes, int n_in,
                              void* d_out, int out_size) {
    const float* xyzs     = (const float*)d_in[0];
    const float* features = (const float*)d_in[1];
    const int*   kg       = (const int*)d_in[2];
    const float* Wk   = (const float*)d_in[3];
    const float* Wv   = (const float*)d_in[4];
    const float* Wq   = (const float*)d_in[5];
    const float* A1   = (const float*)d_in[6];
    const float* b1   = (const float*)d_in[7];
    const float* A2   = (const float*)d_in[8];
    const float* P1   = (const float*)d_in[10];
    const float* bp1  = (const float*)d_in[11];
    const float* P2   = (const float*)d_in[12];
    const float* bp2  = (const float*)d_in[13];
    const float* Wout = (const float*)d_in[14];
    const float* bout = (const float*)d_in[15];
    float* out = (float*)d_out;

    float *pQKV;
    __nv_bfloat16 *pFeatP, *pWcatP, *pWoutP, *pFusedP;
    cudaGetSymbolAddress((void**)&pQKV,    g_QKV);
    cudaGetSymbolAddress((void**)&pFeatP,  g_featP);
    cudaGetSymbolAddress((void**)&pWcatP,  g_WcatP);
    cudaGetSymbolAddress((void**)&pWoutP,  g_WoutP);
    cudaGetSymbolAddress((void**)&pFusedP, g_fusedP);

    setup_kernel<<<CIN + 1, NCAT>>>(Wq, Wk, Wv, A1, P2, b1, bp2);
    setup2_kernel<<<NCAT + HD, 128>>>(Wout);
    convert_feat_kernel<<<NPTS * CIN / 4 / 256, 256>>>(features);

    // QKV: [16384 x 192] @ [384 x 192]^T -> [16384 x 384]
    mma_gemm_kernel<192, 192, 192, NCAT, false>
        <<<dim3(NPTS / 64, NCAT / 64), 128>>>(pFeatP, pWcatP, nullptr, pQKV);

    attn_kernel<<<NPTS / 4, 128>>>(xyzs, kg, A2, P1, bp1, P2, bp2);

    // out: [16384 x 384] @ [128 x 384]^T + bout -> [16384 x 128]
    mma_gemm_kernel<384, 384, 384, COUT, true>
        <<<dim3(NPTS / 64, COUT / 64), 128>>>(pFusedP, pWoutP, bout, out);
}

// round 7
// speedup vs baseline: 1.4299x; 1.0280x over previous
#include <cuda_runtime.h>
#include <cuda_bf16.h>
#include <cstdint>

#define NB   2
#define NN   8192
#define NK   16
#define HD   128
#define CIN  64
#define COUT 128
#define NPTS (NB * NN)   // 16384
#define NCAT 384         // QA|KA|V concatenated

// ---------------- helpers ----------------------------------------------------
__device__ __forceinline__ uint32_t smem_to_u32(const void* p) {
    uint32_t a;
    asm("{ .reg .u64 t; cvta.to.shared.u64 t, %1; cvt.u32.u64 %0, t; }"
        : "=r"(a) : "l"(p));
    return a;
}
#define LDSM_X4(r0, r1, r2, r3, addr) \
    asm volatile("ldmatrix.sync.aligned.m8n8.x4.shared.b16 {%0,%1,%2,%3}, [%4];" \
                 : "=r"(r0), "=r"(r1), "=r"(r2), "=r"(r3) : "r"(addr))
#define MMA_BF16(c, a, b0, b1) \
    asm volatile("mma.sync.aligned.m16n8k16.row.col.f32.bf16.bf16.f32 " \
                 "{%0,%1,%2,%3}, {%4,%5,%6,%7}, {%8,%9}, {%0,%1,%2,%3};" \
                 : "+f"((c)[0]), "+f"((c)[1]), "+f"((c)[2]), "+f"((c)[3]) \
                 : "r"((a)[0]), "r"((a)[1]), "r"((a)[2]), "r"((a)[3]), \
                   "r"(b0), "r"(b1))
#define CP_ASYNC16(dst, src) \
    asm volatile("cp.async.cg.shared.global [%0], [%1], 16;" \
                 :: "r"(dst), "l"(src) : "memory")
#define CP_COMMIT() asm volatile("cp.async.commit_group;" ::: "memory")
#define CP_WAIT(n)  asm volatile("cp.async.wait_group %0;" :: "n"(n) : "memory")
#define SWZ(b) ((b) ^ (((b) >> 3) & 0x70))

// ---------------- scratch globals --------------------------------------------
__device__ float g_Wcat[CIN * NCAT];                       // folded fp32 [k][n]
__device__ float g_P2A1[3 * HD];
__device__ float g_c1[HD];
__device__ __align__(16) float g_QKV[NPTS * NCAT];
__device__ __align__(16) __nv_bfloat16 g_featP[NPTS * 192];    // [Ah|Al|Ah]
__device__ __align__(16) __nv_bfloat16 g_WcatP[NCAT * 192];    // [n][Bh|Bh|Bl]
__device__ __align__(16) __nv_bfloat16 g_WoutP[HD * 384];      // [n][Bh|Bh|Bl]
__device__ __align__(16) __nv_bfloat16 g_fusedP[NPTS * 384];   // [Fh|Fl|Fh]

// ---------------- weight folding (fp32) --------------------------------------
__global__ void setup_kernel(const float* __restrict__ Wq, const float* __restrict__ Wk,
                             const float* __restrict__ Wv, const float* __restrict__ A1,
                             const float* __restrict__ P2, const float* __restrict__ b1,
                             const float* __restrict__ bp2) {
    int c = threadIdx.x;          // 0..383
    int r = blockIdx.x;
    if (r < CIN) {
        float acc;
        if (c < HD) {
            acc = 0.f;
            for (int j = 0; j < HD; j++) acc = fmaf(Wq[r * HD + j], A1[j * HD + c], acc);
        } else if (c < 2 * HD) {
            int cc = c - HD;
            acc = 0.f;
            for (int j = 0; j < HD; j++) acc = fmaf(Wk[r * HD + j], A1[j * HD + cc], acc);
        } else {
            acc = Wv[r * HD + (c - 2 * HD)];
        }
        g_Wcat[r * NCAT + c] = acc;
    } else if (c < HD) {
        for (int rr = 0; rr < 3; rr++) {
            float acc = 0.f;
            for (int j = 0; j < HD; j++) acc = fmaf(P2[rr * HD + j], A1[j * HD + c], acc);
            g_P2A1[rr * HD + c] = acc;
        }
        float acc = b1[c];
        for (int j = 0; j < HD; j++) acc = fmaf(bp2[j], A1[j * HD + c], acc);
        g_c1[c] = acc;
    }
}

// transpose + bf16 hi/lo K-pack of weights.
__global__ void setup2_kernel(const float* __restrict__ Wout) {
    int b = blockIdx.x, t = threadIdx.x;
    if (b < NCAT) {
        if (t < CIN) {
            float w = g_Wcat[t * NCAT + b];
            __nv_bfloat16 h = __float2bfloat16_rn(w);
            __nv_bfloat16 l = __float2bfloat16_rn(w - __bfloat162float(h));
            g_WcatP[b * 192 + t]       = h;
            g_WcatP[b * 192 + 64 + t]  = h;
            g_WcatP[b * 192 + 128 + t] = l;
        }
    } else {
        int n = b - NCAT;
        float w = Wout[t * HD + n];
        __nv_bfloat16 h = __float2bfloat16_rn(w);
        __nv_bfloat16 l = __float2bfloat16_rn(w - __bfloat162float(h));
        g_WoutP[n * 384 + t]       = h;
        g_WoutP[n * 384 + 128 + t] = h;
        g_WoutP[n * 384 + 256 + t] = l;
    }
}

// features -> bf16 hi/lo K-packed [Ah|Al|Ah]
__global__ void convert_feat_kernel(const float* __restrict__ feat) {
    int e = blockIdx.x * 256 + threadIdx.x;     // e < NPTS*CIN/4
    float4 v = ((const float4*)feat)[e];
    int pt = e >> 4, k = (e & 15) * 4;
    __nv_bfloat16 h0 = __float2bfloat16_rn(v.x), h1 = __float2bfloat16_rn(v.y);
    __nv_bfloat16 h2 = __float2bfloat16_rn(v.z), h3 = __float2bfloat16_rn(v.w);
    __nv_bfloat16 l0 = __float2bfloat16_rn(v.x - __bfloat162float(h0));
    __nv_bfloat16 l1 = __float2bfloat16_rn(v.y - __bfloat162float(h1));
    __nv_bfloat16 l2 = __float2bfloat16_rn(v.z - __bfloat162float(h2));
    __nv_bfloat16 l3 = __float2bfloat16_rn(v.w - __bfloat162float(h3));
    __nv_bfloat162 hA = __halves2bfloat162(h0, h1), hB = __halves2bfloat162(h2, h3);
    __nv_bfloat162 lA = __halves2bfloat162(l0, l1), lB = __halves2bfloat162(l2, l3);
    __nv_bfloat162* base = (__nv_bfloat162*)(g_featP + (size_t)pt * 192 + k);
    base[0] = hA; base[1] = hB;
    base[32] = lA; base[33] = lB;          // +64 elems
    base[64] = hA; base[65] = hB;          // +128 elems
}

// ---------------- mma.sync GEMM, 2-stage cp.async pipeline --------------------
// C[M x N] = A'[M x KTOT](bf16) @ B'[N x KTOT](bf16, row=n) + bias, fp32 accum.
// CTA: 128 thr (4 warps), tile 64(M) x 64(N), K chunked by 64, double-buffered.
template <int KTOT, int LDA, int LDB, int LDC, bool HASBIAS>
__global__ void __launch_bounds__(128) mma_gemm_kernel(const __nv_bfloat16* __restrict__ A,
                                                       const __nv_bfloat16* __restrict__ B,
                                                       const float* __restrict__ bias,
                                                       float* __restrict__ C) {
    constexpr int NCH = KTOT / 64;
    __shared__ __align__(16) char sA[2][8192];   // 64 rows x 64 bf16 (swizzled) x 2 stages
    __shared__ __align__(16) char sB[2][8192];

    const int tid = threadIdx.x, wid = tid >> 5, lane = tid & 31;
    const int row0 = blockIdx.x * 64, col0 = blockIdx.y * 64;
    const int wm = (wid & 1) * 32, wn = (wid >> 1) * 32;
    const uint32_t sAb = smem_to_u32(sA), sBb = smem_to_u32(sB);

    float c[2][4][4];
#pragma unroll
    for (int mt = 0; mt < 2; mt++)
#pragma unroll
        for (int nt = 0; nt < 4; nt++)
#pragma unroll
            for (int q = 0; q < 4; q++) c[mt][nt][q] = 0.f;

    const uint32_t lrow = lane & 15;
    const uint32_t lcb  = (lane >> 4) * 16;

    // per-thread load slots: 4 x (A row, 16B chunk) + same for B
    const int lr0 = tid >> 3, lc0 = tid & 7;     // thread covers rows lr0, lr0+16, +32, +48

    auto issue_load = [&](int ch, int st) {
#pragma unroll
        for (int u = 0; u < 4; u++) {
            int r = lr0 + u * 16;
            uint32_t off = SWZ((uint32_t)(r * 128 + lc0 * 16));
            CP_ASYNC16(sAb + st * 8192 + off,
                       A + (size_t)(row0 + r) * LDA + ch * 64 + lc0 * 8);
            CP_ASYNC16(sBb + st * 8192 + off,
                       B + (size_t)(col0 + r) * LDB + ch * 64 + lc0 * 8);
        }
        CP_COMMIT();
    };

    issue_load(0, 0);

#pragma unroll
    for (int ch = 0; ch < NCH; ch++) {
        const int st = ch & 1;
        if (ch + 1 < NCH) {
            issue_load(ch + 1, st ^ 1);
            CP_WAIT(1);
        } else {
            CP_WAIT(0);
        }
        __syncthreads();

#pragma unroll
        for (int k16 = 0; k16 < 4; k16++) {
            uint32_t a[2][4], bf[2][4];
#pragma unroll
            for (int mt = 0; mt < 2; mt++) {
                uint32_t b = SWZ((wm + mt * 16 + lrow) * 128 + k16 * 32 + lcb);
                LDSM_X4(a[mt][0], a[mt][1], a[mt][2], a[mt][3], sAb + st * 8192 + b);
            }
#pragma unroll
            for (int np = 0; np < 2; np++) {
                uint32_t b = SWZ((wn + np * 16 + lrow) * 128 + k16 * 32 + lcb);
                LDSM_X4(bf[np][0], bf[np][1], bf[np][2], bf[np][3], sBb + st * 8192 + b);
            }
#pragma unroll
            for (int mt = 0; mt < 2; mt++) {
#pragma unroll
                for (int nt = 0; nt < 4; nt++)
                    MMA_BF16(c[mt][nt], a[mt], bf[nt >> 1][nt & 1], bf[nt >> 1][(nt & 1) + 2]);
            }
        }
        if (ch + 1 < NCH) __syncthreads();   // protect stage st from next overwrite
    }

    // epilogue
#pragma unroll
    for (int mt = 0; mt < 2; mt++) {
        int r = row0 + wm + mt * 16 + (lane >> 2);
#pragma unroll
        for (int nt = 0; nt < 4; nt++) {
            int cc = col0 + wn + nt * 8 + (lane & 3) * 2;
            float bx = 0.f, by = 0.f;
            if (HASBIAS) { bx = bias[cc]; by = bias[cc + 1]; }
            *(float2*)(C + (size_t)r * LDC + cc) =
                make_float2(c[mt][nt][0] + bx, c[mt][nt][1] + by);
            *(float2*)(C + (size_t)(r + 8) * LDC + cc) =
                make_float2(c[mt][nt][2] + bx, c[mt][nt][3] + by);
        }
    }
}

// ---------------- fused attention kernel: one warp per point ----------------
__global__ void __launch_bounds__(128) attn_kernel(const float* __restrict__ xyzs,
                                                   const int* __restrict__ kg,
                                                   const float* __restrict__ A2,
                                                   const float* __restrict__ P1,
                                                   const float* __restrict__ bp1,
                                                   const float* __restrict__ P2,
                                                   const float* __restrict__ bp2) {
    const unsigned FULL = 0xffffffffu;
    const int warp = threadIdx.x >> 5;
    const int lane = threadIdx.x & 31;
    const int pt   = blockIdx.x * 4 + warp;
    const int bN   = pt & ~(NN - 1);
    const int c0   = lane * 4;

    float hbase[4], p2a1c[3][4], A2c[4][4];
    {
        float4 qa = *(const float4*)(g_QKV + (size_t)pt * NCAT + c0);
        float4 c1 = *(const float4*)(g_c1 + c0);
        hbase[0] = qa.x + c1.x; hbase[1] = qa.y + c1.y;
        hbase[2] = qa.z + c1.z; hbase[3] = qa.w + c1.w;
#pragma unroll
        for (int r = 0; r < 3; r++) {
            float4 v = *(const float4*)(g_P2A1 + r * HD + c0);
            p2a1c[r][0] = v.x; p2a1c[r][1] = v.y; p2a1c[r][2] = v.z; p2a1c[r][3] = v.w;
        }
#pragma unroll
        for (int i = 0; i < 4; i++) {
            float4 a2v = *(const float4*)(A2 + (c0 + i) * 4);
            A2c[i][0] = a2v.x; A2c[i][1] = a2v.y; A2c[i][2] = a2v.z; A2c[i][3] = a2v.w;
        }
    }
    float P1r[9];
#pragma unroll
    for (int i = 0; i < 9; i++) P1r[i] = P1[i];
    float bp1r[3] = {bp1[0], bp1[1], bp1[2]};
    const float cx = xyzs[(size_t)pt * 3 + 0];
    const float cy = xyzs[(size_t)pt * 3 + 1];
    const float cz = xyzs[(size_t)pt * 3 + 2];

    const int idx_l = kg[(size_t)pt * NK + (lane & 15)];

    const bool hi = (lane & 16) != 0;
    const bool b3 = (lane & 8) != 0;

    float lk0 = 0.f, lk1 = 0.f;
    float s0 = 0.f, s1 = 0.f, s2 = 0.f;   // lane-distributed t stash (lane k holds t of nbr k)

#pragma unroll
    for (int k = 0; k < NK; k++) {
        int idx = __shfl_sync(FULL, idx_l, k);
        const float* nx = xyzs + (size_t)(bN + idx) * 3;
        float rx = cx - nx[0], ry = cy - nx[1], rz = cz - nx[2];
        float t0 = fmaxf(fmaf(rx, P1r[0], fmaf(ry, P1r[3], fmaf(rz, P1r[6], bp1r[0]))), 0.f);
        float t1 = fmaxf(fmaf(rx, P1r[1], fmaf(ry, P1r[4], fmaf(rz, P1r[7], bp1r[1]))), 0.f);
        float t2 = fmaxf(fmaf(rx, P1r[2], fmaf(ry, P1r[5], fmaf(rz, P1r[8], bp1r[2]))), 0.f);
        if (lane == k) { s0 = t0; s1 = t1; s2 = t2; }
        float4 ka = *(const float4*)(g_QKV + (size_t)(bN + idx) * NCAT + HD + c0);
        float kav[4] = {ka.x, ka.y, ka.z, ka.w};
        float p0 = 0.f, p1 = 0.f, p2 = 0.f, p3 = 0.f;
#pragma unroll
        for (int i = 0; i < 4; i++) {
            float h = hbase[i] - kav[i];
            h = fmaf(t0, p2a1c[0][i], h);
            h = fmaf(t1, p2a1c[1][i], h);
            h = fmaf(t2, p2a1c[2][i], h);
            float r = fmaxf(h, 0.f);
            p0 = fmaf(r, A2c[i][0], p0);
            p1 = fmaf(r, A2c[i][1], p1);
            p2 = fmaf(r, A2c[i][2], p2);
            p3 = fmaf(r, A2c[i][3], p3);
        }
        float sa = hi ? p0 : p2;
        float sb = hi ? p1 : p3;
        float ra = __shfl_xor_sync(FULL, sa, 16);
        float rb = __shfl_xor_sync(FULL, sb, 16);
        float u0 = (hi ? p2 : p0) + ra;
        float u1 = (hi ? p3 : p1) + rb;
        float sc = b3 ? u0 : u1;
        float rc = __shfl_xor_sync(FULL, sc, 8);
        float ww = (b3 ? u1 : u0) + rc;
        ww += __shfl_xor_sync(FULL, ww, 4);
        ww += __shfl_xor_sync(FULL, ww, 2);
        ww += __shfl_xor_sync(FULL, ww, 1);
        if ((lane & 7) == (k & 7)) {
            if (k < 8) lk0 = ww; else lk1 = ww;
        }
    }

    float mx = fmaxf(lk0, lk1);
    mx = fmaxf(mx, __shfl_xor_sync(FULL, mx, 4));
    mx = fmaxf(mx, __shfl_xor_sync(FULL, mx, 2));
    mx = fmaxf(mx, __shfl_xor_sync(FULL, mx, 1));
    float e0 = __expf(lk0 - mx), e1 = __expf(lk1 - mx);
    float s = e0 + e1;
    s += __shfl_xor_sync(FULL, s, 4);
    s += __shfl_xor_sync(FULL, s, 2);
    s += __shfl_xor_sync(FULL, s, 1);
    float inv = __fdividef(1.f, s);
    float a0 = e0 * inv, a1 = e1 * inv;

    float p2c[3][4], bp2c[4];
#pragma unroll
    for (int r = 0; r < 3; r++) {
        float4 v = *(const float4*)(P2 + r * HD + c0);
        p2c[r][0] = v.x; p2c[r][1] = v.y; p2c[r][2] = v.z; p2c[r][3] = v.w;
    }
    {
        float4 v = *(const float4*)(bp2 + c0);
        bp2c[0] = v.x; bp2c[1] = v.y; bp2c[2] = v.z; bp2c[3] = v.w;
    }

    const int hsrc = lane & 24;

    float accv[4] = {0.f, 0.f, 0.f, 0.f};
#pragma unroll
    for (int k = 0; k < NK; k++) {
        float asel = (k < 8) ? a0 : a1;
        float aw = __shfl_sync(FULL, asel, hsrc | (k & 7));
        int idx = __shfl_sync(FULL, idx_l, k);
        float t0 = __shfl_sync(FULL, s0, k);
        float t1 = __shfl_sync(FULL, s1, k);
        float t2 = __shfl_sync(FULL, s2, k);
        float4 vv = *(const float4*)(g_QKV + (size_t)(bN + idx) * NCAT + 2 * HD + c0);
        float vvv[4] = {vv.x, vv.y, vv.z, vv.w};
#pragma unroll
        for (int i = 0; i < 4; i++) {
            float pe = fmaf(t0, p2c[0][i], fmaf(t1, p2c[1][i], fmaf(t2, p2c[2][i], bp2c[i])));
            accv[i] = fmaf(aw, vvv[i] + pe, accv[i]);
        }
    }
    // write fused K-packed: [Fh | Fl | Fh]
    {
        __nv_bfloat16 h0 = __float2bfloat16_rn(accv[0]);
        __nv_bfloat16 h1 = __float2bfloat16_rn(accv[1]);
        __nv_bfloat16 h2 = __float2bfloat16_rn(accv[2]);
        __nv_bfloat16 h3 = __float2bfloat16_rn(accv[3]);
        __nv_bfloat16 l0 = __float2bfloat16_rn(accv[0] - __bfloat162float(h0));
        __nv_bfloat16 l1 = __float2bfloat16_rn(accv[1] - __bfloat162float(h1));
        __nv_bfloat16 l2 = __float2bfloat16_rn(accv[2] - __bfloat162float(h2));
        __nv_bfloat16 l3 = __float2bfloat16_rn(accv[3] - __bfloat162float(h3));
        __nv_bfloat162 hA = __halves2bfloat162(h0, h1), hB = __halves2bfloat162(h2, h3);
        __nv_bfloat162 lA = __halves2bfloat162(l0, l1), lB = __halves2bfloat162(l2, l3);
        __nv_bfloat162* base = (__nv_bfloat162*)(g_fusedP + (size_t)pt * 384 + c0);
        base[0]  = hA; base[1]  = hB;
        base[64] = lA; base[65] = lB;      // +128 elems
        base[128] = hA; base[129] = hB;    // +256 elems
    }
}

// ======================= launch =============================================
extern "C" void kernel_launch(void* const* d_in, const int* in_sizes, int n_in,
                              void* d_out, int out_size) {
    const float* xyzs     = (const float*)d_in[0];
    const float* features = (const float*)d_in[1];
    const int*   kg       = (const int*)d_in[2];
    const float* Wk   = (const float*)d_in[3];
    const float* Wv   = (const float*)d_in[4];
    const float* Wq   = (const float*)d_in[5];
    const float* A1   = (const float*)d_in[6];
    const float* b1   = (const float*)d_in[7];
    const float* A2   = (const float*)d_in[8];
    const float* P1   = (const float*)d_in[10];
    const float* bp1  = (const float*)d_in[11];
    const float* P2   = (const float*)d_in[12];
    const float* bp2  = (const float*)d_in[13];
    const float* Wout = (const float*)d_in[14];
    const float* bout = (const float*)d_in[15];
    float* out = (float*)d_out;

    float *pQKV;
    __nv_bfloat16 *pFeatP, *pWcatP, *pWoutP, *pFusedP;
    cudaGetSymbolAddress((void**)&pQKV,    g_QKV);
    cudaGetSymbolAddress((void**)&pFeatP,  g_featP);
    cudaGetSymbolAddress((void**)&pWcatP,  g_WcatP);
    cudaGetSymbolAddress((void**)&pWoutP,  g_WoutP);
    cudaGetSymbolAddress((void**)&pFusedP, g_fusedP);

    setup_kernel<<<CIN + 1, NCAT>>>(Wq, Wk, Wv, A1, P2, b1, bp2);
    setup2_kernel<<<NCAT + HD, 128>>>(Wout);
    convert_feat_kernel<<<NPTS * CIN / 4 / 256, 256>>>(features);

    // QKV: [16384 x 192] @ [384 x 192]^T -> [16384 x 384]
    mma_gemm_kernel<192, 192, 192, NCAT, false>
        <<<dim3(NPTS / 64, NCAT / 64), 128>>>(pFeatP, pWcatP, nullptr, pQKV);

    attn_kernel<<<NPTS / 4, 128>>>(xyzs, kg, A2, P1, bp1, P2, bp2);

    // out: [16384 x 384] @ [128 x 384]^T + bout -> [16384 x 128]
    mma_gemm_kernel<384, 384, 384, COUT, true>
        <<<dim3(NPTS / 64, COUT / 64), 128>>>(pFusedP, pWoutP, bout, out);
}

// round 8
// speedup vs baseline: 1.4658x; 1.0251x over previous
#include <cuda_runtime.h>
#include <cuda_bf16.h>
#include <cuda_fp16.h>
#include <cstdint>

#define NB   2
#define NN   8192
#define NK   16
#define HD   128
#define CIN  64
#define COUT 128
#define NPTS (NB * NN)   // 16384
#define NCAT 384         // QA|KA|V concatenated

// ---------------- helpers ----------------------------------------------------
__device__ __forceinline__ uint32_t smem_to_u32(const void* p) {
    uint32_t a;
    asm("{ .reg .u64 t; cvta.to.shared.u64 t, %1; cvt.u32.u64 %0, t; }"
        : "=r"(a) : "l"(p));
    return a;
}
#define LDSM_X4(r0, r1, r2, r3, addr) \
    asm volatile("ldmatrix.sync.aligned.m8n8.x4.shared.b16 {%0,%1,%2,%3}, [%4];" \
                 : "=r"(r0), "=r"(r1), "=r"(r2), "=r"(r3) : "r"(addr))
#define MMA_BF16(c, a, b0, b1) \
    asm volatile("mma.sync.aligned.m16n8k16.row.col.f32.bf16.bf16.f32 " \
                 "{%0,%1,%2,%3}, {%4,%5,%6,%7}, {%8,%9}, {%0,%1,%2,%3};" \
                 : "+f"((c)[0]), "+f"((c)[1]), "+f"((c)[2]), "+f"((c)[3]) \
                 : "r"((a)[0]), "r"((a)[1]), "r"((a)[2]), "r"((a)[3]), \
                   "r"(b0), "r"(b1))
#define CP_ASYNC16(dst, src) \
    asm volatile("cp.async.cg.shared.global [%0], [%1], 16;" \
                 :: "r"(dst), "l"(src) : "memory")
#define CP_COMMIT() asm volatile("cp.async.commit_group;" ::: "memory")
#define CP_WAIT(n)  asm volatile("cp.async.wait_group %0;" :: "n"(n) : "memory")
#define SWZ(b) ((b) ^ (((b) >> 3) & 0x70))

// load 4 contiguous halves -> float4 (8B load)
__device__ __forceinline__ float4 ldh4(const __half* p) {
    uint2 u = *(const uint2*)p;
    float2 fa = __half22float2(*(__half2*)&u.x);
    float2 fb = __half22float2(*(__half2*)&u.y);
    return make_float4(fa.x, fa.y, fb.x, fb.y);
}

// ---------------- scratch globals --------------------------------------------
__device__ float g_Wcat[CIN * NCAT];                       // folded fp32 [k][n]
__device__ float g_P2A1[3 * HD];
__device__ float g_c1[HD];
__device__ __align__(16) __half g_QKVh[NPTS * NCAT];           // fp16 [QA|KA|V]
__device__ __align__(16) __nv_bfloat16 g_featP[NPTS * 192];    // [Ah|Al|Ah]
__device__ __align__(16) __nv_bfloat16 g_WcatP[NCAT * 192];    // [n][Bh|Bh|Bl]
__device__ __align__(16) __nv_bfloat16 g_WoutP[HD * 384];      // [n][Bh|Bh|Bl]
__device__ __align__(16) __nv_bfloat16 g_fusedP[NPTS * 384];   // [Fh|Fl|Fh]

// ---------------- weight folding (fp32) --------------------------------------
__global__ void setup_kernel(const float* __restrict__ Wq, const float* __restrict__ Wk,
                             const float* __restrict__ Wv, const float* __restrict__ A1,
                             const float* __restrict__ P2, const float* __restrict__ b1,
                             const float* __restrict__ bp2) {
    int c = threadIdx.x;          // 0..383
    int r = blockIdx.x;
    if (r < CIN) {
        float acc;
        if (c < HD) {
            acc = 0.f;
            for (int j = 0; j < HD; j++) acc = fmaf(Wq[r * HD + j], A1[j * HD + c], acc);
        } else if (c < 2 * HD) {
            int cc = c - HD;
            acc = 0.f;
            for (int j = 0; j < HD; j++) acc = fmaf(Wk[r * HD + j], A1[j * HD + cc], acc);
        } else {
            acc = Wv[r * HD + (c - 2 * HD)];
        }
        g_Wcat[r * NCAT + c] = acc;
    } else if (c < HD) {
        for (int rr = 0; rr < 3; rr++) {
            float acc = 0.f;
            for (int j = 0; j < HD; j++) acc = fmaf(P2[rr * HD + j], A1[j * HD + c], acc);
            g_P2A1[rr * HD + c] = acc;
        }
        float acc = b1[c];
        for (int j = 0; j < HD; j++) acc = fmaf(bp2[j], A1[j * HD + c], acc);
        g_c1[c] = acc;
    }
}

// transpose + bf16 hi/lo K-pack of weights.
__global__ void setup2_kernel(const float* __restrict__ Wout) {
    int b = blockIdx.x, t = threadIdx.x;
    if (b < NCAT) {
        if (t < CIN) {
            float w = g_Wcat[t * NCAT + b];
            __nv_bfloat16 h = __float2bfloat16_rn(w);
            __nv_bfloat16 l = __float2bfloat16_rn(w - __bfloat162float(h));
            g_WcatP[b * 192 + t]       = h;
            g_WcatP[b * 192 + 64 + t]  = h;
            g_WcatP[b * 192 + 128 + t] = l;
        }
    } else {
        int n = b - NCAT;
        float w = Wout[t * HD + n];
        __nv_bfloat16 h = __float2bfloat16_rn(w);
        __nv_bfloat16 l = __float2bfloat16_rn(w - __bfloat162float(h));
        g_WoutP[n * 384 + t]       = h;
        g_WoutP[n * 384 + 128 + t] = h;
        g_WoutP[n * 384 + 256 + t] = l;
    }
}

// features -> bf16 hi/lo K-packed [Ah|Al|Ah]
__global__ void convert_feat_kernel(const float* __restrict__ feat) {
    int e = blockIdx.x * 256 + threadIdx.x;     // e < NPTS*CIN/4
    float4 v = ((const float4*)feat)[e];
    int pt = e >> 4, k = (e & 15) * 4;
    __nv_bfloat16 h0 = __float2bfloat16_rn(v.x), h1 = __float2bfloat16_rn(v.y);
    __nv_bfloat16 h2 = __float2bfloat16_rn(v.z), h3 = __float2bfloat16_rn(v.w);
    __nv_bfloat16 l0 = __float2bfloat16_rn(v.x - __bfloat162float(h0));
    __nv_bfloat16 l1 = __float2bfloat16_rn(v.y - __bfloat162float(h1));
    __nv_bfloat16 l2 = __float2bfloat16_rn(v.z - __bfloat162float(h2));
    __nv_bfloat16 l3 = __float2bfloat16_rn(v.w - __bfloat162float(h3));
    __nv_bfloat162 hA = __halves2bfloat162(h0, h1), hB = __halves2bfloat162(h2, h3);
    __nv_bfloat162 lA = __halves2bfloat162(l0, l1), lB = __halves2bfloat162(l2, l3);
    __nv_bfloat162* base = (__nv_bfloat162*)(g_featP + (size_t)pt * 192 + k);
    base[0] = hA; base[1] = hB;
    base[32] = lA; base[33] = lB;          // +64 elems
    base[64] = hA; base[65] = hB;          // +128 elems
}

// ---------------- mma.sync GEMM, 2-stage cp.async pipeline --------------------
// C[M x N] = A'[M x KTOT](bf16) @ B'[N x KTOT](bf16, row=n) + bias, fp32 accum.
// CTA: 128 thr (4 warps), tile 64(M) x 64(N), K chunked by 64, double-buffered.
// HALFOUT: store C as fp16 (no bias); else fp32 (+bias if HASBIAS).
template <int KTOT, int LDA, int LDB, int LDC, bool HASBIAS, bool HALFOUT>
__global__ void __launch_bounds__(128) mma_gemm_kernel(const __nv_bfloat16* __restrict__ A,
                                                       const __nv_bfloat16* __restrict__ B,
                                                       const float* __restrict__ bias,
                                                       void* __restrict__ Cv) {
    constexpr int NCH = KTOT / 64;
    __shared__ __align__(16) char sA[2][8192];
    __shared__ __align__(16) char sB[2][8192];

    const int tid = threadIdx.x, wid = tid >> 5, lane = tid & 31;
    const int row0 = blockIdx.x * 64, col0 = blockIdx.y * 64;
    const int wm = (wid & 1) * 32, wn = (wid >> 1) * 32;
    const uint32_t sAb = smem_to_u32(sA), sBb = smem_to_u32(sB);

    float c[2][4][4];
#pragma unroll
    for (int mt = 0; mt < 2; mt++)
#pragma unroll
        for (int nt = 0; nt < 4; nt++)
#pragma unroll
            for (int q = 0; q < 4; q++) c[mt][nt][q] = 0.f;

    const uint32_t lrow = lane & 15;
    const uint32_t lcb  = (lane >> 4) * 16;
    const int lr0 = tid >> 3, lc0 = tid & 7;

    auto issue_load = [&](int ch, int st) {
#pragma unroll
        for (int u = 0; u < 4; u++) {
            int r = lr0 + u * 16;
            uint32_t off = SWZ((uint32_t)(r * 128 + lc0 * 16));
            CP_ASYNC16(sAb + st * 8192 + off,
                       A + (size_t)(row0 + r) * LDA + ch * 64 + lc0 * 8);
            CP_ASYNC16(sBb + st * 8192 + off,
                       B + (size_t)(col0 + r) * LDB + ch * 64 + lc0 * 8);
        }
        CP_COMMIT();
    };

    issue_load(0, 0);

#pragma unroll
    for (int ch = 0; ch < NCH; ch++) {
        const int st = ch & 1;
        if (ch + 1 < NCH) {
            issue_load(ch + 1, st ^ 1);
            CP_WAIT(1);
        } else {
            CP_WAIT(0);
        }
        __syncthreads();

#pragma unroll
        for (int k16 = 0; k16 < 4; k16++) {
            uint32_t a[2][4], bf[2][4];
#pragma unroll
            for (int mt = 0; mt < 2; mt++) {
                uint32_t b = SWZ((wm + mt * 16 + lrow) * 128 + k16 * 32 + lcb);
                LDSM_X4(a[mt][0], a[mt][1], a[mt][2], a[mt][3], sAb + st * 8192 + b);
            }
#pragma unroll
            for (int np = 0; np < 2; np++) {
                uint32_t b = SWZ((wn + np * 16 + lrow) * 128 + k16 * 32 + lcb);
                LDSM_X4(bf[np][0], bf[np][1], bf[np][2], bf[np][3], sBb + st * 8192 + b);
            }
#pragma unroll
            for (int mt = 0; mt < 2; mt++) {
#pragma unroll
                for (int nt = 0; nt < 4; nt++)
                    MMA_BF16(c[mt][nt], a[mt], bf[nt >> 1][nt & 1], bf[nt >> 1][(nt & 1) + 2]);
            }
        }
        if (ch + 1 < NCH) __syncthreads();
    }

    // epilogue
#pragma unroll
    for (int mt = 0; mt < 2; mt++) {
        int r = row0 + wm + mt * 16 + (lane >> 2);
#pragma unroll
        for (int nt = 0; nt < 4; nt++) {
            int cc = col0 + wn + nt * 8 + (lane & 3) * 2;
            if (HALFOUT) {
                __half* C = (__half*)Cv;
                *(__half2*)(C + (size_t)r * LDC + cc) =
                    __floats2half2_rn(c[mt][nt][0], c[mt][nt][1]);
                *(__half2*)(C + (size_t)(r + 8) * LDC + cc) =
                    __floats2half2_rn(c[mt][nt][2], c[mt][nt][3]);
            } else {
                float* C = (float*)Cv;
                float bx = 0.f, by = 0.f;
                if (HASBIAS) { bx = bias[cc]; by = bias[cc + 1]; }
                *(float2*)(C + (size_t)r * LDC + cc) =
                    make_float2(c[mt][nt][0] + bx, c[mt][nt][1] + by);
                *(float2*)(C + (size_t)(r + 8) * LDC + cc) =
                    make_float2(c[mt][nt][2] + bx, c[mt][nt][3] + by);
            }
        }
    }
}

// ---------------- fused attention kernel: one warp per point ----------------
__global__ void __launch_bounds__(128) attn_kernel(const float* __restrict__ xyzs,
                                                   const int* __restrict__ kg,
                                                   const float* __restrict__ A2,
                                                   const float* __restrict__ P1,
                                                   const float* __restrict__ bp1,
                                                   const float* __restrict__ P2,
                                                   const float* __restrict__ bp2) {
    const unsigned FULL = 0xffffffffu;
    const int warp = threadIdx.x >> 5;
    const int lane = threadIdx.x & 31;
    const int pt   = blockIdx.x * 4 + warp;
    const int bN   = pt & ~(NN - 1);
    const int c0   = lane * 4;

    float hbase[4], p2a1c[3][4], A2c[4][4];
    {
        float4 qa = ldh4(g_QKVh + (size_t)pt * NCAT + c0);
        float4 c1 = *(const float4*)(g_c1 + c0);
        hbase[0] = qa.x + c1.x; hbase[1] = qa.y + c1.y;
        hbase[2] = qa.z + c1.z; hbase[3] = qa.w + c1.w;
#pragma unroll
        for (int r = 0; r < 3; r++) {
            float4 v = *(const float4*)(g_P2A1 + r * HD + c0);
            p2a1c[r][0] = v.x; p2a1c[r][1] = v.y; p2a1c[r][2] = v.z; p2a1c[r][3] = v.w;
        }
#pragma unroll
        for (int i = 0; i < 4; i++) {
            float4 a2v = *(const float4*)(A2 + (c0 + i) * 4);
            A2c[i][0] = a2v.x; A2c[i][1] = a2v.y; A2c[i][2] = a2v.z; A2c[i][3] = a2v.w;
        }
    }
    float P1r[9];
#pragma unroll
    for (int i = 0; i < 9; i++) P1r[i] = P1[i];
    float bp1r[3] = {bp1[0], bp1[1], bp1[2]};
    const float cx = xyzs[(size_t)pt * 3 + 0];
    const float cy = xyzs[(size_t)pt * 3 + 1];
    const float cz = xyzs[(size_t)pt * 3 + 2];

    const int idx_l = kg[(size_t)pt * NK + (lane & 15)];

    const bool hi = (lane & 16) != 0;
    const bool b3 = (lane & 8) != 0;

    float lk0 = 0.f, lk1 = 0.f;
    float s0 = 0.f, s1 = 0.f, s2 = 0.f;   // lane-distributed t stash

#pragma unroll
    for (int k = 0; k < NK; k++) {
        int idx = __shfl_sync(FULL, idx_l, k);
        const float* nx = xyzs + (size_t)(bN + idx) * 3;
        float rx = cx - nx[0], ry = cy - nx[1], rz = cz - nx[2];
        float t0 = fmaxf(fmaf(rx, P1r[0], fmaf(ry, P1r[3], fmaf(rz, P1r[6], bp1r[0]))), 0.f);
        float t1 = fmaxf(fmaf(rx, P1r[1], fmaf(ry, P1r[4], fmaf(rz, P1r[7], bp1r[1]))), 0.f);
        float t2 = fmaxf(fmaf(rx, P1r[2], fmaf(ry, P1r[5], fmaf(rz, P1r[8], bp1r[2]))), 0.f);
        if (lane == k) { s0 = t0; s1 = t1; s2 = t2; }
        float4 ka = ldh4(g_QKVh + (size_t)(bN + idx) * NCAT + HD + c0);
        float kav[4] = {ka.x, ka.y, ka.z, ka.w};
        float p0 = 0.f, p1 = 0.f, p2 = 0.f, p3 = 0.f;
#pragma unroll
        for (int i = 0; i < 4; i++) {
            float h = hbase[i] - kav[i];
            h = fmaf(t0, p2a1c[0][i], h);
            h = fmaf(t1, p2a1c[1][i], h);
            h = fmaf(t2, p2a1c[2][i], h);
            float r = fmaxf(h, 0.f);
            p0 = fmaf(r, A2c[i][0], p0);
            p1 = fmaf(r, A2c[i][1], p1);
            p2 = fmaf(r, A2c[i][2], p2);
            p3 = fmaf(r, A2c[i][3], p3);
        }
        float sa = hi ? p0 : p2;
        float sb = hi ? p1 : p3;
        float ra = __shfl_xor_sync(FULL, sa, 16);
        float rb = __shfl_xor_sync(FULL, sb, 16);
        float u0 = (hi ? p2 : p0) + ra;
        float u1 = (hi ? p3 : p1) + rb;
        float sc = b3 ? u0 : u1;
        float rc = __shfl_xor_sync(FULL, sc, 8);
        float ww = (b3 ? u1 : u0) + rc;
        ww += __shfl_xor_sync(FULL, ww, 4);
        ww += __shfl_xor_sync(FULL, ww, 2);
        ww += __shfl_xor_sync(FULL, ww, 1);
        if ((lane & 7) == (k & 7)) {
            if (k < 8) lk0 = ww; else lk1 = ww;
        }
    }

    float mx = fmaxf(lk0, lk1);
    mx = fmaxf(mx, __shfl_xor_sync(FULL, mx, 4));
    mx = fmaxf(mx, __shfl_xor_sync(FULL, mx, 2));
    mx = fmaxf(mx, __shfl_xor_sync(FULL, mx, 1));
    float e0 = __expf(lk0 - mx), e1 = __expf(lk1 - mx);
    float s = e0 + e1;
    s += __shfl_xor_sync(FULL, s, 4);
    s += __shfl_xor_sync(FULL, s, 2);
    s += __shfl_xor_sync(FULL, s, 1);
    float inv = __fdividef(1.f, s);
    float a0 = e0 * inv, a1 = e1 * inv;

    float p2c[3][4], bp2c[4];
#pragma unroll
    for (int r = 0; r < 3; r++) {
        float4 v = *(const float4*)(P2 + r * HD + c0);
        p2c[r][0] = v.x; p2c[r][1] = v.y; p2c[r][2] = v.z; p2c[r][3] = v.w;
    }
    {
        float4 v = *(const float4*)(bp2 + c0);
        bp2c[0] = v.x; bp2c[1] = v.y; bp2c[2] = v.z; bp2c[3] = v.w;
    }

    const int hsrc = lane & 24;

    float accv[4] = {0.f, 0.f, 0.f, 0.f};
#pragma unroll
    for (int k = 0; k < NK; k++) {
        float asel = (k < 8) ? a0 : a1;
        float aw = __shfl_sync(FULL, asel, hsrc | (k & 7));
        int idx = __shfl_sync(FULL, idx_l, k);
        float t0 = __shfl_sync(FULL, s0, k);
        float t1 = __shfl_sync(FULL, s1, k);
        float t2 = __shfl_sync(FULL, s2, k);
        float4 vv = ldh4(g_QKVh + (size_t)(bN + idx) * NCAT + 2 * HD + c0);
        float vvv[4] = {vv.x, vv.y, vv.z, vv.w};
#pragma unroll
        for (int i = 0; i < 4; i++) {
            float pe = fmaf(t0, p2c[0][i], fmaf(t1, p2c[1][i], fmaf(t2, p2c[2][i], bp2c[i])));
            accv[i] = fmaf(aw, vvv[i] + pe, accv[i]);
        }
    }
    // write fused K-packed: [Fh | Fl | Fh]
    {
        __nv_bfloat16 h0 = __float2bfloat16_rn(accv[0]);
        __nv_bfloat16 h1 = __float2bfloat16_rn(accv[1]);
        __nv_bfloat16 h2 = __float2bfloat16_rn(accv[2]);
        __nv_bfloat16 h3 = __float2bfloat16_rn(accv[3]);
        __nv_bfloat16 l0 = __float2bfloat16_rn(accv[0] - __bfloat162float(h0));
        __nv_bfloat16 l1 = __float2bfloat16_rn(accv[1] - __bfloat162float(h1));
        __nv_bfloat16 l2 = __float2bfloat16_rn(accv[2] - __bfloat162float(h2));
        __nv_bfloat16 l3 = __float2bfloat16_rn(accv[3] - __bfloat162float(h3));
        __nv_bfloat162 hA = __halves2bfloat162(h0, h1), hB = __halves2bfloat162(h2, h3);
        __nv_bfloat162 lA = __halves2bfloat162(l0, l1), lB = __halves2bfloat162(l2, l3);
        __nv_bfloat162* base = (__nv_bfloat162*)(g_fusedP + (size_t)pt * 384 + c0);
        base[0]  = hA; base[1]  = hB;
        base[64] = lA; base[65] = lB;      // +128 elems
        base[128] = hA; base[129] = hB;    // +256 elems
    }
}

// ======================= launch =============================================
extern "C" void kernel_launch(void* const* d_in, const int* in_sizes, int n_in,
                              void* d_out, int out_size) {
    const float* xyzs     = (const float*)d_in[0];
    const float* features = (const float*)d_in[1];
    const int*   kg       = (const int*)d_in[2];
    const float* Wk   = (const float*)d_in[3];
    const float* Wv   = (const float*)d_in[4];
    const float* Wq   = (const float*)d_in[5];
    const float* A1   = (const float*)d_in[6];
    const float* b1   = (const float*)d_in[7];
    const float* A2   = (const float*)d_in[8];
    const float* P1   = (const float*)d_in[10];
    const float* bp1  = (const float*)d_in[11];
    const float* P2   = (const float*)d_in[12];
    const float* bp2  = (const float*)d_in[13];
    const float* Wout = (const float*)d_in[14];
    const float* bout = (const float*)d_in[15];
    float* out = (float*)d_out;

    __half* pQKVh;
    __nv_bfloat16 *pFeatP, *pWcatP, *pWoutP, *pFusedP;
    cudaGetSymbolAddress((void**)&pQKVh,   g_QKVh);
    cudaGetSymbolAddress((void**)&pFeatP,  g_featP);
    cudaGetSymbolAddress((void**)&pWcatP,  g_WcatP);
    cudaGetSymbolAddress((void**)&pWoutP,  g_WoutP);
    cudaGetSymbolAddress((void**)&pFusedP, g_fusedP);

    setup_kernel<<<CIN + 1, NCAT>>>(Wq, Wk, Wv, A1, P2, b1, bp2);
    setup2_kernel<<<NCAT + HD, 128>>>(Wout);
    convert_feat_kernel<<<NPTS * CIN / 4 / 256, 256>>>(features);

    // QKV: [16384 x 192] @ [384 x 192]^T -> fp16 [16384 x 384]
    mma_gemm_kernel<192, 192, 192, NCAT, false, true>
        <<<dim3(NPTS / 64, NCAT / 64), 128>>>(pFeatP, pWcatP, nullptr, pQKVh);

    attn_kernel<<<NPTS / 4, 128>>>(xyzs, kg, A2, P1, bp1, P2, bp2);

    // out: [16384 x 384] @ [128 x 384]^T + bout -> fp32 [16384 x 128]
    mma_gemm_kernel<384, 384, 384, COUT, true, false>
        <<<dim3(NPTS / 64, COUT / 64), 128>>>(pFusedP, pWoutP, bout, out);
}

// round 9
// speedup vs baseline: 1.6270x; 1.1100x over previous
#include <cuda_runtime.h>
#include <cuda_fp16.h>
#include <cstdint>

#define NB   2
#define NN   8192
#define NK   16
#define HD   128
#define CIN  64
#define COUT 128
#define NPTS (NB * NN)   // 16384
#define NCAT 384         // QA|KA|V concatenated

// ---------------- helpers ----------------------------------------------------
__device__ __forceinline__ uint32_t smem_to_u32(const void* p) {
    uint32_t a;
    asm("{ .reg .u64 t; cvta.to.shared.u64 t, %1; cvt.u32.u64 %0, t; }"
        : "=r"(a) : "l"(p));
    return a;
}
#define LDSM_X4(r0, r1, r2, r3, addr) \
    asm volatile("ldmatrix.sync.aligned.m8n8.x4.shared.b16 {%0,%1,%2,%3}, [%4];" \
                 : "=r"(r0), "=r"(r1), "=r"(r2), "=r"(r3) : "r"(addr))
#define MMA_F16(c, a, b0, b1) \
    asm volatile("mma.sync.aligned.m16n8k16.row.col.f32.f16.f16.f32 " \
                 "{%0,%1,%2,%3}, {%4,%5,%6,%7}, {%8,%9}, {%0,%1,%2,%3};" \
                 : "+f"((c)[0]), "+f"((c)[1]), "+f"((c)[2]), "+f"((c)[3]) \
                 : "r"((a)[0]), "r"((a)[1]), "r"((a)[2]), "r"((a)[3]), \
                   "r"(b0), "r"(b1))
#define CP_ASYNC16(dst, src) \
    asm volatile("cp.async.cg.shared.global [%0], [%1], 16;" \
                 :: "r"(dst), "l"(src) : "memory")
#define CP_COMMIT() asm volatile("cp.async.commit_group;" ::: "memory")
#define CP_WAIT(n)  asm volatile("cp.async.wait_group %0;" :: "n"(n) : "memory")
#define SWZ(b) ((b) ^ (((b) >> 3) & 0x70))

// load 4 contiguous halves -> float4 (8B load)
__device__ __forceinline__ float4 ldh4(const __half* p) {
    uint2 u = *(const uint2*)p;
    float2 fa = __half22float2(*(__half2*)&u.x);
    float2 fb = __half22float2(*(__half2*)&u.y);
    return make_float4(fa.x, fa.y, fb.x, fb.y);
}

// ---------------- scratch globals --------------------------------------------
__device__ float g_P2A1[3 * HD];
__device__ float g_c1[HD];
__device__ __align__(16) __half g_QKVh[NPTS * NCAT];       // fp16 [QA|KA|V]
__device__ __align__(16) __half g_feath[NPTS * CIN];       // fp16 features
__device__ __align__(16) __half g_WcatPh[NCAT * CIN];      // fp16 [n][k] folded
__device__ __align__(16) __half g_WoutPh[HD * HD];         // fp16 [n][k]
__device__ __align__(16) __half g_fusedh[NPTS * HD];       // fp16 fused

// ---------------- setup: fold weights, write transposed fp16 -----------------
// blocks 0..63   : row r of folded Wcat -> g_WcatPh[c][r]
// block  64      : P2A1 (3x128) and c1 (fp32, used by attn)
// blocks 65..192 : Wout col n -> g_WoutPh[n][t]
__global__ void setup_kernel(const float* __restrict__ Wq, const float* __restrict__ Wk,
                             const float* __restrict__ Wv, const float* __restrict__ A1,
                             const float* __restrict__ P2, const float* __restrict__ b1,
                             const float* __restrict__ bp2, const float* __restrict__ Wout) {
    int c = threadIdx.x;          // 0..383
    int blk = blockIdx.x;
    if (blk < CIN) {
        int r = blk;
        float acc;
        if (c < HD) {
            acc = 0.f;
            for (int j = 0; j < HD; j++) acc = fmaf(Wq[r * HD + j], A1[j * HD + c], acc);
        } else if (c < 2 * HD) {
            int cc = c - HD;
            acc = 0.f;
            for (int j = 0; j < HD; j++) acc = fmaf(Wk[r * HD + j], A1[j * HD + cc], acc);
        } else {
            acc = Wv[r * HD + (c - 2 * HD)];
        }
        g_WcatPh[c * CIN + r] = __float2half_rn(acc);
    } else if (blk == CIN) {
        if (c < HD) {
            for (int rr = 0; rr < 3; rr++) {
                float acc = 0.f;
                for (int j = 0; j < HD; j++) acc = fmaf(P2[rr * HD + j], A1[j * HD + c], acc);
                g_P2A1[rr * HD + c] = acc;
            }
            float acc = b1[c];
            for (int j = 0; j < HD; j++) acc = fmaf(bp2[j], A1[j * HD + c], acc);
            g_c1[c] = acc;
        }
    } else {
        int n = blk - CIN - 1;    // 0..127
        if (c < HD)
            g_WoutPh[n * HD + c] = __float2half_rn(Wout[c * HD + n]);
    }
}

// features -> fp16
__global__ void convert_feat_kernel(const float* __restrict__ feat) {
    int e = blockIdx.x * 256 + threadIdx.x;     // e < NPTS*CIN/4
    float4 v = ((const float4*)feat)[e];
    uint2 o;
    *(__half2*)&o.x = __floats2half2_rn(v.x, v.y);
    *(__half2*)&o.y = __floats2half2_rn(v.z, v.w);
    ((uint2*)g_feath)[e] = o;
}

// ---------------- fp16 mma GEMM, 2-stage cp.async pipeline --------------------
// C[M x N] = A[M x KTOT](fp16) @ B[N x KTOT](fp16, row=n) + bias, fp32 accum.
// CTA: 128 thr (4 warps), tile 64(M) x 64(N), K chunked by 64, double-buffered.
template <int KTOT, int LDA, int LDB, int LDC, bool HASBIAS, bool HALFOUT>
__global__ void __launch_bounds__(128) mma_gemm_kernel(const __half* __restrict__ A,
                                                       const __half* __restrict__ B,
                                                       const float* __restrict__ bias,
                                                       void* __restrict__ Cv) {
    constexpr int NCH = KTOT / 64;
    __shared__ __align__(16) char sA[2][8192];
    __shared__ __align__(16) char sB[2][8192];

    const int tid = threadIdx.x, wid = tid >> 5, lane = tid & 31;
    const int row0 = blockIdx.x * 64, col0 = blockIdx.y * 64;
    const int wm = (wid & 1) * 32, wn = (wid >> 1) * 32;
    const uint32_t sAb = smem_to_u32(sA), sBb = smem_to_u32(sB);

    float c[2][4][4];
#pragma unroll
    for (int mt = 0; mt < 2; mt++)
#pragma unroll
        for (int nt = 0; nt < 4; nt++)
#pragma unroll
            for (int q = 0; q < 4; q++) c[mt][nt][q] = 0.f;

    const uint32_t lrow = lane & 15;
    const uint32_t lcb  = (lane >> 4) * 16;
    const int lr0 = tid >> 3, lc0 = tid & 7;

    auto issue_load = [&](int ch, int st) {
#pragma unroll
        for (int u = 0; u < 4; u++) {
            int r = lr0 + u * 16;
            uint32_t off = SWZ((uint32_t)(r * 128 + lc0 * 16));
            CP_ASYNC16(sAb + st * 8192 + off,
                       A + (size_t)(row0 + r) * LDA + ch * 64 + lc0 * 8);
            CP_ASYNC16(sBb + st * 8192 + off,
                       B + (size_t)(col0 + r) * LDB + ch * 64 + lc0 * 8);
        }
        CP_COMMIT();
    };

    issue_load(0, 0);

#pragma unroll
    for (int ch = 0; ch < NCH; ch++) {
        const int st = ch & 1;
        if (ch + 1 < NCH) {
            issue_load(ch + 1, st ^ 1);
            CP_WAIT(1);
        } else {
            CP_WAIT(0);
        }
        __syncthreads();

#pragma unroll
        for (int k16 = 0; k16 < 4; k16++) {
            uint32_t a[2][4], bf[2][4];
#pragma unroll
            for (int mt = 0; mt < 2; mt++) {
                uint32_t b = SWZ((wm + mt * 16 + lrow) * 128 + k16 * 32 + lcb);
                LDSM_X4(a[mt][0], a[mt][1], a[mt][2], a[mt][3], sAb + st * 8192 + b);
            }
#pragma unroll
            for (int np = 0; np < 2; np++) {
                uint32_t b = SWZ((wn + np * 16 + lrow) * 128 + k16 * 32 + lcb);
                LDSM_X4(bf[np][0], bf[np][1], bf[np][2], bf[np][3], sBb + st * 8192 + b);
            }
#pragma unroll
            for (int mt = 0; mt < 2; mt++) {
#pragma unroll
                for (int nt = 0; nt < 4; nt++)
                    MMA_F16(c[mt][nt], a[mt], bf[nt >> 1][nt & 1], bf[nt >> 1][(nt & 1) + 2]);
            }
        }
        if (ch + 1 < NCH) __syncthreads();
    }

    // epilogue
#pragma unroll
    for (int mt = 0; mt < 2; mt++) {
        int r = row0 + wm + mt * 16 + (lane >> 2);
#pragma unroll
        for (int nt = 0; nt < 4; nt++) {
            int cc = col0 + wn + nt * 8 + (lane & 3) * 2;
            if (HALFOUT) {
                __half* C = (__half*)Cv;
                *(__half2*)(C + (size_t)r * LDC + cc) =
                    __floats2half2_rn(c[mt][nt][0], c[mt][nt][1]);
                *(__half2*)(C + (size_t)(r + 8) * LDC + cc) =
                    __floats2half2_rn(c[mt][nt][2], c[mt][nt][3]);
            } else {
                float* C = (float*)Cv;
                float bx = 0.f, by = 0.f;
                if (HASBIAS) { bx = bias[cc]; by = bias[cc + 1]; }
                *(float2*)(C + (size_t)r * LDC + cc) =
                    make_float2(c[mt][nt][0] + bx, c[mt][nt][1] + by);
                *(float2*)(C + (size_t)(r + 8) * LDC + cc) =
                    make_float2(c[mt][nt][2] + bx, c[mt][nt][3] + by);
            }
        }
    }
}

// ---------------- fused attention kernel: one warp per point ----------------
__global__ void __launch_bounds__(128) attn_kernel(const float* __restrict__ xyzs,
                                                   const int* __restrict__ kg,
                                                   const float* __restrict__ A2,
                                                   const float* __restrict__ P1,
                                                   const float* __restrict__ bp1,
                                                   const float* __restrict__ P2,
                                                   const float* __restrict__ bp2) {
    const unsigned FULL = 0xffffffffu;
    const int warp = threadIdx.x >> 5;
    const int lane = threadIdx.x & 31;
    const int pt   = blockIdx.x * 4 + warp;
    const int bN   = pt & ~(NN - 1);
    const int c0   = lane * 4;

    float hbase[4], p2a1c[3][4], A2c[4][4];
    {
        float4 qa = ldh4(g_QKVh + (size_t)pt * NCAT + c0);
        float4 c1 = *(const float4*)(g_c1 + c0);
        hbase[0] = qa.x + c1.x; hbase[1] = qa.y + c1.y;
        hbase[2] = qa.z + c1.z; hbase[3] = qa.w + c1.w;
#pragma unroll
        for (int r = 0; r < 3; r++) {
            float4 v = *(const float4*)(g_P2A1 + r * HD + c0);
            p2a1c[r][0] = v.x; p2a1c[r][1] = v.y; p2a1c[r][2] = v.z; p2a1c[r][3] = v.w;
        }
#pragma unroll
        for (int i = 0; i < 4; i++) {
            float4 a2v = *(const float4*)(A2 + (c0 + i) * 4);
            A2c[i][0] = a2v.x; A2c[i][1] = a2v.y; A2c[i][2] = a2v.z; A2c[i][3] = a2v.w;
        }
    }
    float P1r[9];
#pragma unroll
    for (int i = 0; i < 9; i++) P1r[i] = P1[i];
    float bp1r[3] = {bp1[0], bp1[1], bp1[2]};
    const float cx = xyzs[(size_t)pt * 3 + 0];
    const float cy = xyzs[(size_t)pt * 3 + 1];
    const float cz = xyzs[(size_t)pt * 3 + 2];

    const int idx_l = kg[(size_t)pt * NK + (lane & 15)];

    const bool hi = (lane & 16) != 0;
    const bool b3 = (lane & 8) != 0;

    float lk0 = 0.f, lk1 = 0.f;
    float s0 = 0.f, s1 = 0.f, s2 = 0.f;   // lane-distributed t stash

#pragma unroll
    for (int k = 0; k < NK; k++) {
        int idx = __shfl_sync(FULL, idx_l, k);
        const float* nx = xyzs + (size_t)(bN + idx) * 3;
        float rx = cx - nx[0], ry = cy - nx[1], rz = cz - nx[2];
        float t0 = fmaxf(fmaf(rx, P1r[0], fmaf(ry, P1r[3], fmaf(rz, P1r[6], bp1r[0]))), 0.f);
        float t1 = fmaxf(fmaf(rx, P1r[1], fmaf(ry, P1r[4], fmaf(rz, P1r[7], bp1r[1]))), 0.f);
        float t2 = fmaxf(fmaf(rx, P1r[2], fmaf(ry, P1r[5], fmaf(rz, P1r[8], bp1r[2]))), 0.f);
        if (lane == k) { s0 = t0; s1 = t1; s2 = t2; }
        float4 ka = ldh4(g_QKVh + (size_t)(bN + idx) * NCAT + HD + c0);
        float kav[4] = {ka.x, ka.y, ka.z, ka.w};
        float p0 = 0.f, p1 = 0.f, p2 = 0.f, p3 = 0.f;
#pragma unroll
        for (int i = 0; i < 4; i++) {
            float h = hbase[i] - kav[i];
            h = fmaf(t0, p2a1c[0][i], h);
            h = fmaf(t1, p2a1c[1][i], h);
            h = fmaf(t2, p2a1c[2][i], h);
            float r = fmaxf(h, 0.f);
            p0 = fmaf(r, A2c[i][0], p0);
            p1 = fmaf(r, A2c[i][1], p1);
            p2 = fmaf(r, A2c[i][2], p2);
            p3 = fmaf(r, A2c[i][3], p3);
        }
        float sa = hi ? p0 : p2;
        float sb = hi ? p1 : p3;
        float ra = __shfl_xor_sync(FULL, sa, 16);
        float rb = __shfl_xor_sync(FULL, sb, 16);
        float u0 = (hi ? p2 : p0) + ra;
        float u1 = (hi ? p3 : p1) + rb;
        float sc = b3 ? u0 : u1;
        float rc = __shfl_xor_sync(FULL, sc, 8);
        float ww = (b3 ? u1 : u0) + rc;
        ww += __shfl_xor_sync(FULL, ww, 4);
        ww += __shfl_xor_sync(FULL, ww, 2);
        ww += __shfl_xor_sync(FULL, ww, 1);
        if ((lane & 7) == (k & 7)) {
            if (k < 8) lk0 = ww; else lk1 = ww;
        }
    }

    float mx = fmaxf(lk0, lk1);
    mx = fmaxf(mx, __shfl_xor_sync(FULL, mx, 4));
    mx = fmaxf(mx, __shfl_xor_sync(FULL, mx, 2));
    mx = fmaxf(mx, __shfl_xor_sync(FULL, mx, 1));
    float e0 = __expf(lk0 - mx), e1 = __expf(lk1 - mx);
    float s = e0 + e1;
    s += __shfl_xor_sync(FULL, s, 4);
    s += __shfl_xor_sync(FULL, s, 2);
    s += __shfl_xor_sync(FULL, s, 1);
    float inv = __fdividef(1.f, s);
    float a0 = e0 * inv, a1 = e1 * inv;

    float p2c[3][4], bp2c[4];
#pragma unroll
    for (int r = 0; r < 3; r++) {
        float4 v = *(const float4*)(P2 + r * HD + c0);
        p2c[r][0] = v.x; p2c[r][1] = v.y; p2c[r][2] = v.z; p2c[r][3] = v.w;
    }
    {
        float4 v = *(const float4*)(bp2 + c0);
        bp2c[0] = v.x; bp2c[1] = v.y; bp2c[2] = v.z; bp2c[3] = v.w;
    }

    const int hsrc = lane & 24;

    float accv[4] = {0.f, 0.f, 0.f, 0.f};
#pragma unroll
    for (int k = 0; k < NK; k++) {
        float asel = (k < 8) ? a0 : a1;
        float aw = __shfl_sync(FULL, asel, hsrc | (k & 7));
        int idx = __shfl_sync(FULL, idx_l, k);
        float t0 = __shfl_sync(FULL, s0, k);
        float t1 = __shfl_sync(FULL, s1, k);
        float t2 = __shfl_sync(FULL, s2, k);
        float4 vv = ldh4(g_QKVh + (size_t)(bN + idx) * NCAT + 2 * HD + c0);
        float vvv[4] = {vv.x, vv.y, vv.z, vv.w};
#pragma unroll
        for (int i = 0; i < 4; i++) {
            float pe = fmaf(t0, p2c[0][i], fmaf(t1, p2c[1][i], fmaf(t2, p2c[2][i], bp2c[i])));
            accv[i] = fmaf(aw, vvv[i] + pe, accv[i]);
        }
    }
    // write fused as fp16
    {
        uint2 o;
        *(__half2*)&o.x = __floats2half2_rn(accv[0], accv[1]);
        *(__half2*)&o.y = __floats2half2_rn(accv[2], accv[3]);
        *(uint2*)(g_fusedh + (size_t)pt * HD + c0) = o;
    }
}

// ======================= launch =============================================
extern "C" void kernel_launch(void* const* d_in, const int* in_sizes, int n_in,
                              void* d_out, int out_size) {
    const float* xyzs     = (const float*)d_in[0];
    const float* features = (const float*)d_in[1];
    const int*   kg       = (const int*)d_in[2];
    const float* Wk   = (const float*)d_in[3];
    const float* Wv   = (const float*)d_in[4];
    const float* Wq   = (const float*)d_in[5];
    const float* A1   = (const float*)d_in[6];
    const float* b1   = (const float*)d_in[7];
    const float* A2   = (const float*)d_in[8];
    const float* P1   = (const float*)d_in[10];
    const float* bp1  = (const float*)d_in[11];
    const float* P2   = (const float*)d_in[12];
    const float* bp2  = (const float*)d_in[13];
    const float* Wout = (const float*)d_in[14];
    const float* bout = (const float*)d_in[15];
    float* out = (float*)d_out;

    __half *pQKVh, *pFeath, *pWcatPh, *pWoutPh, *pFusedh;
    cudaGetSymbolAddress((void**)&pQKVh,   g_QKVh);
    cudaGetSymbolAddress((void**)&pFeath,  g_feath);
    cudaGetSymbolAddress((void**)&pWcatPh, g_WcatPh);
    cudaGetSymbolAddress((void**)&pWoutPh, g_WoutPh);
    cudaGetSymbolAddress((void**)&pFusedh, g_fusedh);

    setup_kernel<<<CIN + 1 + HD, NCAT>>>(Wq, Wk, Wv, A1, P2, b1, bp2, Wout);
    convert_feat_kernel<<<NPTS * CIN / 4 / 256, 256>>>(features);

    // QKV: [16384 x 64] @ [384 x 64]^T -> fp16 [16384 x 384]
    mma_gemm_kernel<CIN, CIN, CIN, NCAT, false, true>
        <<<dim3(NPTS / 64, NCAT / 64), 128>>>(pFeath, pWcatPh, nullptr, pQKVh);

    attn_kernel<<<NPTS / 4, 128>>>(xyzs, kg, A2, P1, bp1, P2, bp2);

    // out: [16384 x 128] @ [128 x 128]^T + bout -> fp32 [16384 x 128]
    mma_gemm_kernel<HD, HD, HD, COUT, true, false>
        <<<dim3(NPTS / 64, COUT / 64), 128>>>(pFusedh, pWoutPh, bout, out);
}

// round 10
// speedup vs baseline: 1.9606x; 1.2050x over previous
#include <cuda_runtime.h>
#include <cuda_fp16.h>
#include <cstdint>

#define NB   2
#define NN   8192
#define NK   16
#define HD   128
#define CIN  64
#define COUT 128
#define NPTS (NB * NN)   // 16384
#define NCAT 384         // QA|KA|V concatenated

// ---------------- helpers ----------------------------------------------------
__device__ __forceinline__ uint32_t smem_to_u32(const void* p) {
    uint32_t a;
    asm("{ .reg .u64 t; cvta.to.shared.u64 t, %1; cvt.u32.u64 %0, t; }"
        : "=r"(a) : "l"(p));
    return a;
}
#define LDSM_X4(r0, r1, r2, r3, addr) \
    asm volatile("ldmatrix.sync.aligned.m8n8.x4.shared.b16 {%0,%1,%2,%3}, [%4];" \
                 : "=r"(r0), "=r"(r1), "=r"(r2), "=r"(r3) : "r"(addr))
#define MMA_F16(c, a, b0, b1) \
    asm volatile("mma.sync.aligned.m16n8k16.row.col.f32.f16.f16.f32 " \
                 "{%0,%1,%2,%3}, {%4,%5,%6,%7}, {%8,%9}, {%0,%1,%2,%3};" \
                 : "+f"((c)[0]), "+f"((c)[1]), "+f"((c)[2]), "+f"((c)[3]) \
                 : "r"((a)[0]), "r"((a)[1]), "r"((a)[2]), "r"((a)[3]), \
                   "r"(b0), "r"(b1))
#define CP_ASYNC16(dst, src) \
    asm volatile("cp.async.cg.shared.global [%0], [%1], 16;" \
                 :: "r"(dst), "l"(src) : "memory")
#define CP_COMMIT() asm volatile("cp.async.commit_group;" ::: "memory")
#define CP_WAIT(n)  asm volatile("cp.async.wait_group %0;" :: "n"(n) : "memory")
#define SWZ(b) ((b) ^ (((b) >> 3) & 0x70))

// load 4 contiguous halves -> float4 (8B load)
__device__ __forceinline__ float4 ldh4(const __half* p) {
    uint2 u = *(const uint2*)p;
    float2 fa = __half22float2(*(__half2*)&u.x);
    float2 fb = __half22float2(*(__half2*)&u.y);
    return make_float4(fa.x, fa.y, fb.x, fb.y);
}

// ---------------- scratch globals --------------------------------------------
__device__ float g_P2A1[3 * HD];
__device__ float g_c1[HD];
__device__ __align__(16) __half g_QKVh[NPTS * NCAT];       // fp16 [QA|KA|V]
__device__ __align__(16) __half g_feath[NPTS * CIN];       // fp16 features
__device__ __align__(16) __half g_WcatPh[NCAT * CIN];      // fp16 [n][k] folded
__device__ __align__(16) __half g_WoutPh[HD * HD];         // fp16 [n][k]
__device__ __align__(16) __half g_fusedh[NPTS * HD];       // fp16 fused

// ---------------- setup: fold weights, write transposed fp16 -----------------
__global__ void setup_kernel(const float* __restrict__ Wq, const float* __restrict__ Wk,
                             const float* __restrict__ Wv, const float* __restrict__ A1,
                             const float* __restrict__ P2, const float* __restrict__ b1,
                             const float* __restrict__ bp2, const float* __restrict__ Wout) {
    int c = threadIdx.x;          // 0..383
    int blk = blockIdx.x;
    if (blk < CIN) {
        int r = blk;
        float acc;
        if (c < HD) {
            acc = 0.f;
            for (int j = 0; j < HD; j++) acc = fmaf(Wq[r * HD + j], A1[j * HD + c], acc);
        } else if (c < 2 * HD) {
            int cc = c - HD;
            acc = 0.f;
            for (int j = 0; j < HD; j++) acc = fmaf(Wk[r * HD + j], A1[j * HD + cc], acc);
        } else {
            acc = Wv[r * HD + (c - 2 * HD)];
        }
        g_WcatPh[c * CIN + r] = __float2half_rn(acc);
    } else if (blk == CIN) {
        if (c < HD) {
            for (int rr = 0; rr < 3; rr++) {
                float acc = 0.f;
                for (int j = 0; j < HD; j++) acc = fmaf(P2[rr * HD + j], A1[j * HD + c], acc);
                g_P2A1[rr * HD + c] = acc;
            }
            float acc = b1[c];
            for (int j = 0; j < HD; j++) acc = fmaf(bp2[j], A1[j * HD + c], acc);
            g_c1[c] = acc;
        }
    } else {
        int n = blk - CIN - 1;    // 0..127
        if (c < HD)
            g_WoutPh[n * HD + c] = __float2half_rn(Wout[c * HD + n]);
    }
}

// features -> fp16
__global__ void convert_feat_kernel(const float* __restrict__ feat) {
    int e = blockIdx.x * 256 + threadIdx.x;     // e < NPTS*CIN/4
    float4 v = ((const float4*)feat)[e];
    uint2 o;
    *(__half2*)&o.x = __floats2half2_rn(v.x, v.y);
    *(__half2*)&o.y = __floats2half2_rn(v.z, v.w);
    ((uint2*)g_feath)[e] = o;
}

// ---------------- fp16 mma GEMM, 2-stage cp.async pipeline --------------------
template <int KTOT, int LDA, int LDB, int LDC, bool HASBIAS, bool HALFOUT>
__global__ void __launch_bounds__(128) mma_gemm_kernel(const __half* __restrict__ A,
                                                       const __half* __restrict__ B,
                                                       const float* __restrict__ bias,
                                                       void* __restrict__ Cv) {
    constexpr int NCH = KTOT / 64;
    __shared__ __align__(16) char sA[2][8192];
    __shared__ __align__(16) char sB[2][8192];

    const int tid = threadIdx.x, wid = tid >> 5, lane = tid & 31;
    const int row0 = blockIdx.x * 64, col0 = blockIdx.y * 64;
    const int wm = (wid & 1) * 32, wn = (wid >> 1) * 32;
    const uint32_t sAb = smem_to_u32(sA), sBb = smem_to_u32(sB);

    float c[2][4][4];
#pragma unroll
    for (int mt = 0; mt < 2; mt++)
#pragma unroll
        for (int nt = 0; nt < 4; nt++)
#pragma unroll
            for (int q = 0; q < 4; q++) c[mt][nt][q] = 0.f;

    const uint32_t lrow = lane & 15;
    const uint32_t lcb  = (lane >> 4) * 16;
    const int lr0 = tid >> 3, lc0 = tid & 7;

    auto issue_load = [&](int ch, int st) {
#pragma unroll
        for (int u = 0; u < 4; u++) {
            int r = lr0 + u * 16;
            uint32_t off = SWZ((uint32_t)(r * 128 + lc0 * 16));
            CP_ASYNC16(sAb + st * 8192 + off,
                       A + (size_t)(row0 + r) * LDA + ch * 64 + lc0 * 8);
            CP_ASYNC16(sBb + st * 8192 + off,
                       B + (size_t)(col0 + r) * LDB + ch * 64 + lc0 * 8);
        }
        CP_COMMIT();
    };

    issue_load(0, 0);

#pragma unroll
    for (int ch = 0; ch < NCH; ch++) {
        const int st = ch & 1;
        if (ch + 1 < NCH) {
            issue_load(ch + 1, st ^ 1);
            CP_WAIT(1);
        } else {
            CP_WAIT(0);
        }
        __syncthreads();

#pragma unroll
        for (int k16 = 0; k16 < 4; k16++) {
            uint32_t a[2][4], bf[2][4];
#pragma unroll
            for (int mt = 0; mt < 2; mt++) {
                uint32_t b = SWZ((wm + mt * 16 + lrow) * 128 + k16 * 32 + lcb);
                LDSM_X4(a[mt][0], a[mt][1], a[mt][2], a[mt][3], sAb + st * 8192 + b);
            }
#pragma unroll
            for (int np = 0; np < 2; np++) {
                uint32_t b = SWZ((wn + np * 16 + lrow) * 128 + k16 * 32 + lcb);
                LDSM_X4(bf[np][0], bf[np][1], bf[np][2], bf[np][3], sBb + st * 8192 + b);
            }
#pragma unroll
            for (int mt = 0; mt < 2; mt++) {
#pragma unroll
                for (int nt = 0; nt < 4; nt++)
                    MMA_F16(c[mt][nt], a[mt], bf[nt >> 1][nt & 1], bf[nt >> 1][(nt & 1) + 2]);
            }
        }
        if (ch + 1 < NCH) __syncthreads();
    }

    // epilogue
#pragma unroll
    for (int mt = 0; mt < 2; mt++) {
        int r = row0 + wm + mt * 16 + (lane >> 2);
#pragma unroll
        for (int nt = 0; nt < 4; nt++) {
            int cc = col0 + wn + nt * 8 + (lane & 3) * 2;
            if (HALFOUT) {
                __half* C = (__half*)Cv;
                *(__half2*)(C + (size_t)r * LDC + cc) =
                    __floats2half2_rn(c[mt][nt][0], c[mt][nt][1]);
                *(__half2*)(C + (size_t)(r + 8) * LDC + cc) =
                    __floats2half2_rn(c[mt][nt][2], c[mt][nt][3]);
            } else {
                float* C = (float*)Cv;
                float bx = 0.f, by = 0.f;
                if (HASBIAS) { bx = bias[cc]; by = bias[cc + 1]; }
                *(float2*)(C + (size_t)r * LDC + cc) =
                    make_float2(c[mt][nt][0] + bx, c[mt][nt][1] + by);
                *(float2*)(C + (size_t)(r + 8) * LDC + cc) =
                    make_float2(c[mt][nt][2] + bx, c[mt][nt][3] + by);
            }
        }
    }
}

// ---------------- fused attention kernel: one warp per point ----------------
// lane owns channels lane*4..lane*4+3 (one head: h = lane>>3).
// Upfront, lane l computes the position-MLP t(k=l&15) and the QKV row offset
// for neighbor l&15; the neighbor loops just shuffle these in.
__global__ void __launch_bounds__(128) attn_kernel(const float* __restrict__ xyzs,
                                                   const int* __restrict__ kg,
                                                   const float* __restrict__ A2,
                                                   const float* __restrict__ P1,
                                                   const float* __restrict__ bp1,
                                                   const float* __restrict__ P2,
                                                   const float* __restrict__ bp2) {
    const unsigned FULL = 0xffffffffu;
    const int warp = threadIdx.x >> 5;
    const int lane = threadIdx.x & 31;
    const int pt   = blockIdx.x * 4 + warp;
    const int bN   = pt & ~(NN - 1);
    const int c0   = lane * 4;

    // ---- upfront: per-lane neighbor prep (lane l -> neighbor l&15) ----
    int rowoff_l;                 // (bN + idx) * NCAT  (fits in int32)
    float t0_l, t1_l, t2_l;       // pos-MLP hidden for neighbor l&15
    {
        int idx = kg[(size_t)pt * NK + (lane & 15)];
        rowoff_l = (bN + idx) * NCAT;
        const float* nx = xyzs + (size_t)(bN + idx) * 3;
        float cx = xyzs[(size_t)pt * 3 + 0];
        float cy = xyzs[(size_t)pt * 3 + 1];
        float cz = xyzs[(size_t)pt * 3 + 2];
        float rx = cx - nx[0], ry = cy - nx[1], rz = cz - nx[2];
        t0_l = fmaxf(fmaf(rx, P1[0], fmaf(ry, P1[3], fmaf(rz, P1[6], bp1[0]))), 0.f);
        t1_l = fmaxf(fmaf(rx, P1[1], fmaf(ry, P1[4], fmaf(rz, P1[7], bp1[1]))), 0.f);
        t2_l = fmaxf(fmaf(rx, P1[2], fmaf(ry, P1[5], fmaf(rz, P1[8], bp1[2]))), 0.f);
    }

    // per-lane channel constants
    float hbase[4], p2a1c[3][4], A2c[4][4];
    {
        float4 qa = ldh4(g_QKVh + (size_t)pt * NCAT + c0);
        float4 c1 = *(const float4*)(g_c1 + c0);
        hbase[0] = qa.x + c1.x; hbase[1] = qa.y + c1.y;
        hbase[2] = qa.z + c1.z; hbase[3] = qa.w + c1.w;
#pragma unroll
        for (int r = 0; r < 3; r++) {
            float4 v = *(const float4*)(g_P2A1 + r * HD + c0);
            p2a1c[r][0] = v.x; p2a1c[r][1] = v.y; p2a1c[r][2] = v.z; p2a1c[r][3] = v.w;
        }
#pragma unroll
        for (int i = 0; i < 4; i++) {
            float4 a2v = *(const float4*)(A2 + (c0 + i) * 4);
            A2c[i][0] = a2v.x; A2c[i][1] = a2v.y; A2c[i][2] = a2v.z; A2c[i][3] = a2v.w;
        }
    }

    const bool hi = (lane & 16) != 0;
    const bool b3 = (lane & 8) != 0;

    float lk0 = 0.f, lk1 = 0.f;

    // ---- pass 1: per-neighbor logits ----
#pragma unroll
    for (int k = 0; k < NK; k++) {
        int rowoff = __shfl_sync(FULL, rowoff_l, k);
        float t0 = __shfl_sync(FULL, t0_l, k);
        float t1 = __shfl_sync(FULL, t1_l, k);
        float t2 = __shfl_sync(FULL, t2_l, k);
        float4 ka = ldh4(g_QKVh + rowoff + HD + c0);
        float kav[4] = {ka.x, ka.y, ka.z, ka.w};
        float p0 = 0.f, p1 = 0.f, p2 = 0.f, p3 = 0.f;
#pragma unroll
        for (int i = 0; i < 4; i++) {
            float h = hbase[i] - kav[i];
            h = fmaf(t0, p2a1c[0][i], h);
            h = fmaf(t1, p2a1c[1][i], h);
            h = fmaf(t2, p2a1c[2][i], h);
            float r = fmaxf(h, 0.f);
            p0 = fmaf(r, A2c[i][0], p0);
            p1 = fmaf(r, A2c[i][1], p1);
            p2 = fmaf(r, A2c[i][2], p2);
            p3 = fmaf(r, A2c[i][3], p3);
        }
        // split-head reduction: 6 shuffles
        float sa = hi ? p0 : p2;
        float sb = hi ? p1 : p3;
        float ra = __shfl_xor_sync(FULL, sa, 16);
        float rb = __shfl_xor_sync(FULL, sb, 16);
        float u0 = (hi ? p2 : p0) + ra;
        float u1 = (hi ? p3 : p1) + rb;
        float sc = b3 ? u0 : u1;
        float rc = __shfl_xor_sync(FULL, sc, 8);
        float ww = (b3 ? u1 : u0) + rc;
        ww += __shfl_xor_sync(FULL, ww, 4);
        ww += __shfl_xor_sync(FULL, ww, 2);
        ww += __shfl_xor_sync(FULL, ww, 1);
        if ((lane & 7) == (k & 7)) {
            if (k < 8) lk0 = ww; else lk1 = ww;
        }
    }

    // ---- softmax: head h in 8-lane group [8h, 8h+7], 2 logits/lane ----
    float mx = fmaxf(lk0, lk1);
    mx = fmaxf(mx, __shfl_xor_sync(FULL, mx, 4));
    mx = fmaxf(mx, __shfl_xor_sync(FULL, mx, 2));
    mx = fmaxf(mx, __shfl_xor_sync(FULL, mx, 1));
    float e0 = __expf(lk0 - mx), e1 = __expf(lk1 - mx);
    float s = e0 + e1;
    s += __shfl_xor_sync(FULL, s, 4);
    s += __shfl_xor_sync(FULL, s, 2);
    s += __shfl_xor_sync(FULL, s, 1);
    float inv = __fdividef(1.f, s);
    float a0 = e0 * inv, a1 = e1 * inv;   // attn(h=lane>>3, k=(lane&7)[+8])

    // ---- factored pe reduction:  S_r(h) = sum_k attn(h,k) * t_r(k),  S3 = sum_k attn ----
    float S0, S1, S2, S3;
    {
        int kk = lane & 7;
        float ua = __shfl_sync(FULL, t0_l, kk);
        float ub = __shfl_sync(FULL, t0_l, kk + 8);
        S0 = a0 * ua + a1 * ub;
        ua = __shfl_sync(FULL, t1_l, kk);
        ub = __shfl_sync(FULL, t1_l, kk + 8);
        S1 = a0 * ua + a1 * ub;
        ua = __shfl_sync(FULL, t2_l, kk);
        ub = __shfl_sync(FULL, t2_l, kk + 8);
        S2 = a0 * ua + a1 * ub;
        S3 = a0 + a1;
#pragma unroll
        for (int m = 4; m >= 1; m >>= 1) {
            S0 += __shfl_xor_sync(FULL, S0, m);
            S1 += __shfl_xor_sync(FULL, S1, m);
            S2 += __shfl_xor_sync(FULL, S2, m);
            S3 += __shfl_xor_sync(FULL, S3, m);
        }
    }

    // accv init = S0*P2row0 + S1*P2row1 + S2*P2row2 + S3*bp2  (per channel)
    float accv[4];
    {
        float4 v0 = *(const float4*)(P2 + 0 * HD + c0);
        float4 v1 = *(const float4*)(P2 + 1 * HD + c0);
        float4 v2 = *(const float4*)(P2 + 2 * HD + c0);
        float4 vb = *(const float4*)(bp2 + c0);
        accv[0] = fmaf(S0, v0.x, fmaf(S1, v1.x, fmaf(S2, v2.x, S3 * vb.x)));
        accv[1] = fmaf(S0, v0.y, fmaf(S1, v1.y, fmaf(S2, v2.y, S3 * vb.y)));
        accv[2] = fmaf(S0, v0.z, fmaf(S1, v1.z, fmaf(S2, v2.z, S3 * vb.z)));
        accv[3] = fmaf(S0, v0.w, fmaf(S1, v1.w, fmaf(S2, v2.w, S3 * vb.w)));
    }

    const int hsrc = lane & 24;   // 8 * head(lane)

    // ---- pass 2: weighted V reduce only ----
#pragma unroll
    for (int k = 0; k < NK; k++) {
        float asel = (k < 8) ? a0 : a1;
        float aw = __shfl_sync(FULL, asel, hsrc | (k & 7));
        int rowoff = __shfl_sync(FULL, rowoff_l, k);
        float4 vv = ldh4(g_QKVh + rowoff + 2 * HD + c0);
        accv[0] = fmaf(aw, vv.x, accv[0]);
        accv[1] = fmaf(aw, vv.y, accv[1]);
        accv[2] = fmaf(aw, vv.z, accv[2]);
        accv[3] = fmaf(aw, vv.w, accv[3]);
    }

    // write fused as fp16
    {
        uint2 o;
        *(__half2*)&o.x = __floats2half2_rn(accv[0], accv[1]);
        *(__half2*)&o.y = __floats2half2_rn(accv[2], accv[3]);
        *(uint2*)(g_fusedh + (size_t)pt * HD + c0) = o;
    }
}

// ======================= launch =============================================
extern "C" void kernel_launch(void* const* d_in, const int* in_sizes, int n_in,
                              void* d_out, int out_size) {
    const float* xyzs     = (const float*)d_in[0];
    const float* features = (const float*)d_in[1];
    const int*   kg       = (const int*)d_in[2];
    const float* Wk   = (const float*)d_in[3];
    const float* Wv   = (const float*)d_in[4];
    const float* Wq   = (const float*)d_in[5];
    const float* A1   = (const float*)d_in[6];
    const float* b1   = (const float*)d_in[7];
    const float* A2   = (const float*)d_in[8];
    const float* P1   = (const float*)d_in[10];
    const float* bp1  = (const float*)d_in[11];
    const float* P2   = (const float*)d_in[12];
    const float* bp2  = (const float*)d_in[13];
    const float* Wout = (const float*)d_in[14];
    const float* bout = (const float*)d_in[15];
    float* out = (float*)d_out;

    __half *pQKVh, *pFeath, *pWcatPh, *pWoutPh, *pFusedh;
    cudaGetSymbolAddress((void**)&pQKVh,   g_QKVh);
    cudaGetSymbolAddress((void**)&pFeath,  g_feath);
    cudaGetSymbolAddress((void**)&pWcatPh, g_WcatPh);
    cudaGetSymbolAddress((void**)&pWoutPh, g_WoutPh);
    cudaGetSymbolAddress((void**)&pFusedh, g_fusedh);

    setup_kernel<<<CIN + 1 + HD, NCAT>>>(Wq, Wk, Wv, A1, P2, b1, bp2, Wout);
    convert_feat_kernel<<<NPTS * CIN / 4 / 256, 256>>>(features);

    // QKV: [16384 x 64] @ [384 x 64]^T -> fp16 [16384 x 384]
    mma_gemm_kernel<CIN, CIN, CIN, NCAT, false, true>
        <<<dim3(NPTS / 64, NCAT / 64), 128>>>(pFeath, pWcatPh, nullptr, pQKVh);

    attn_kernel<<<NPTS / 4, 128>>>(xyzs, kg, A2, P1, bp1, P2, bp2);

    // out: [16384 x 128] @ [128 x 128]^T + bout -> fp32 [16384 x 128]
    mma_gemm_kernel<HD, HD, HD, COUT, true, false>
        <<<dim3(NPTS / 64, COUT / 64), 128>>>(pFusedh, pWoutPh, bout, out);
}

// round 11
// speedup vs baseline: 2.1395x; 1.0912x over previous
#include <cuda_runtime.h>
#include <cuda_fp16.h>
#include <cstdint>

#define NB   2
#define NN   8192
#define NK   16
#define HD   128
#define CIN  64
#define COUT 128
#define NPTS (NB * NN)   // 16384
#define NCAT 384         // QA|KA|V concatenated

// ---------------- helpers ----------------------------------------------------
__device__ __forceinline__ uint32_t smem_to_u32(const void* p) {
    uint32_t a;
    asm("{ .reg .u64 t; cvta.to.shared.u64 t, %1; cvt.u32.u64 %0, t; }"
        : "=r"(a) : "l"(p));
    return a;
}
#define LDSM_X4(r0, r1, r2, r3, addr) \
    asm volatile("ldmatrix.sync.aligned.m8n8.x4.shared.b16 {%0,%1,%2,%3}, [%4];" \
                 : "=r"(r0), "=r"(r1), "=r"(r2), "=r"(r3) : "r"(addr))
#define MMA_F16(c, a, b0, b1) \
    asm volatile("mma.sync.aligned.m16n8k16.row.col.f32.f16.f16.f32 " \
                 "{%0,%1,%2,%3}, {%4,%5,%6,%7}, {%8,%9}, {%0,%1,%2,%3};" \
                 : "+f"((c)[0]), "+f"((c)[1]), "+f"((c)[2]), "+f"((c)[3]) \
                 : "r"((a)[0]), "r"((a)[1]), "r"((a)[2]), "r"((a)[3]), \
                   "r"(b0), "r"(b1))
#define CP_ASYNC16(dst, src) \
    asm volatile("cp.async.cg.shared.global [%0], [%1], 16;" \
                 :: "r"(dst), "l"(src) : "memory")
#define CP_COMMIT() asm volatile("cp.async.commit_group;" ::: "memory")
#define CP_WAIT(n)  asm volatile("cp.async.wait_group %0;" :: "n"(n) : "memory")
#define SWZ(b) ((b) ^ (((b) >> 3) & 0x70))

__device__ __forceinline__ float4 ldh4(const __half* p) {
    uint2 u = *(const uint2*)p;
    float2 fa = __half22float2(*(__half2*)&u.x);
    float2 fb = __half22float2(*(__half2*)&u.y);
    return make_float4(fa.x, fa.y, fb.x, fb.y);
}
__device__ __forceinline__ __half2 shfl_h2(__half2 v, int src) {
    uint32_t u = *(uint32_t*)&v;
    u = __shfl_sync(0xffffffffu, u, src);
    return *(__half2*)&u;
}
__device__ __forceinline__ __half2 shfl_xor_h2(__half2 v, int m) {
    uint32_t u = *(uint32_t*)&v;
    u = __shfl_xor_sync(0xffffffffu, u, m);
    return *(__half2*)&u;
}

// ---------------- scratch globals --------------------------------------------
__device__ float g_P2A1[3 * HD];
__device__ float g_c1[HD];
__device__ __align__(16) __half g_QKVh[NPTS * NCAT];       // fp16 [QA|KA|V]
__device__ __align__(16) __half g_feath[NPTS * CIN];       // fp16 features
__device__ __align__(16) __half g_WcatPh[NCAT * CIN];      // fp16 [n][k] folded
__device__ __align__(16) __half g_WoutPh[HD * HD];         // fp16 [n][k]
__device__ __align__(16) __half g_fusedh[NPTS * HD];       // fp16 fused

// ---------------- setup + feature convert (merged, one launch) ---------------
// blocks 0..63    : row r of folded Wcat -> g_WcatPh[c][r]
// block  64       : P2A1 (3x128) and c1
// blocks 65..192  : Wout col n -> g_WoutPh[n][t]
// blocks 193..    : features fp32 -> fp16 (float4 granularity)
#define SETUP_BLKS (CIN + 1 + HD)          // 193
#define CONV_ITEMS (NPTS * CIN / 4)        // 262144
__global__ void setup_kernel(const float* __restrict__ Wq, const float* __restrict__ Wk,
                             const float* __restrict__ Wv, const float* __restrict__ A1,
                             const float* __restrict__ P2, const float* __restrict__ b1,
                             const float* __restrict__ bp2, const float* __restrict__ Wout,
                             const float* __restrict__ feat) {
    int c = threadIdx.x;          // 0..383
    int blk = blockIdx.x;
    if (blk < CIN) {
        int r = blk;
        float acc;
        if (c < HD) {
            acc = 0.f;
            for (int j = 0; j < HD; j++) acc = fmaf(Wq[r * HD + j], A1[j * HD + c], acc);
        } else if (c < 2 * HD) {
            int cc = c - HD;
            acc = 0.f;
            for (int j = 0; j < HD; j++) acc = fmaf(Wk[r * HD + j], A1[j * HD + cc], acc);
        } else {
            acc = Wv[r * HD + (c - 2 * HD)];
        }
        g_WcatPh[c * CIN + r] = __float2half_rn(acc);
    } else if (blk == CIN) {
        if (c < HD) {
            for (int rr = 0; rr < 3; rr++) {
                float acc = 0.f;
                for (int j = 0; j < HD; j++) acc = fmaf(P2[rr * HD + j], A1[j * HD + c], acc);
                g_P2A1[rr * HD + c] = acc;
            }
            float acc = b1[c];
            for (int j = 0; j < HD; j++) acc = fmaf(bp2[j], A1[j * HD + c], acc);
            g_c1[c] = acc;
        }
    } else if (blk < SETUP_BLKS) {
        int n = blk - CIN - 1;    // 0..127
        if (c < HD)
            g_WoutPh[n * HD + c] = __float2half_rn(Wout[c * HD + n]);
    } else {
        int e = (blk - SETUP_BLKS) * 384 + c;
        if (e < CONV_ITEMS) {
            float4 v = ((const float4*)feat)[e];
            uint2 o;
            *(__half2*)&o.x = __floats2half2_rn(v.x, v.y);
            *(__half2*)&o.y = __floats2half2_rn(v.z, v.w);
            ((uint2*)g_feath)[e] = o;
        }
    }
}

// ---------------- fp16 mma GEMM, 2-stage cp.async pipeline --------------------
template <int KTOT, int LDA, int LDB, int LDC, bool HASBIAS, bool HALFOUT>
__global__ void __launch_bounds__(128) mma_gemm_kernel(const __half* __restrict__ A,
                                                       const __half* __restrict__ B,
                                                       const float* __restrict__ bias,
                                                       void* __restrict__ Cv) {
    constexpr int NCH = KTOT / 64;
    __shared__ __align__(16) char sA[2][8192];
    __shared__ __align__(16) char sB[2][8192];

    const int tid = threadIdx.x, wid = tid >> 5, lane = tid & 31;
    const int row0 = blockIdx.x * 64, col0 = blockIdx.y * 64;
    const int wm = (wid & 1) * 32, wn = (wid >> 1) * 32;
    const uint32_t sAb = smem_to_u32(sA), sBb = smem_to_u32(sB);

    float c[2][4][4];
#pragma unroll
    for (int mt = 0; mt < 2; mt++)
#pragma unroll
        for (int nt = 0; nt < 4; nt++)
#pragma unroll
            for (int q = 0; q < 4; q++) c[mt][nt][q] = 0.f;

    const uint32_t lrow = lane & 15;
    const uint32_t lcb  = (lane >> 4) * 16;
    const int lr0 = tid >> 3, lc0 = tid & 7;

    auto issue_load = [&](int ch, int st) {
#pragma unroll
        for (int u = 0; u < 4; u++) {
            int r = lr0 + u * 16;
            uint32_t off = SWZ((uint32_t)(r * 128 + lc0 * 16));
            CP_ASYNC16(sAb + st * 8192 + off,
                       A + (size_t)(row0 + r) * LDA + ch * 64 + lc0 * 8);
            CP_ASYNC16(sBb + st * 8192 + off,
                       B + (size_t)(col0 + r) * LDB + ch * 64 + lc0 * 8);
        }
        CP_COMMIT();
    };

    issue_load(0, 0);

#pragma unroll
    for (int ch = 0; ch < NCH; ch++) {
        const int st = ch & 1;
        if (ch + 1 < NCH) {
            issue_load(ch + 1, st ^ 1);
            CP_WAIT(1);
        } else {
            CP_WAIT(0);
        }
        __syncthreads();

#pragma unroll
        for (int k16 = 0; k16 < 4; k16++) {
            uint32_t a[2][4], bf[2][4];
#pragma unroll
            for (int mt = 0; mt < 2; mt++) {
                uint32_t b = SWZ((wm + mt * 16 + lrow) * 128 + k16 * 32 + lcb);
                LDSM_X4(a[mt][0], a[mt][1], a[mt][2], a[mt][3], sAb + st * 8192 + b);
            }
#pragma unroll
            for (int np = 0; np < 2; np++) {
                uint32_t b = SWZ((wn + np * 16 + lrow) * 128 + k16 * 32 + lcb);
                LDSM_X4(bf[np][0], bf[np][1], bf[np][2], bf[np][3], sBb + st * 8192 + b);
            }
#pragma unroll
            for (int mt = 0; mt < 2; mt++) {
#pragma unroll
                for (int nt = 0; nt < 4; nt++)
                    MMA_F16(c[mt][nt], a[mt], bf[nt >> 1][nt & 1], bf[nt >> 1][(nt & 1) + 2]);
            }
        }
        if (ch + 1 < NCH) __syncthreads();
    }

    // epilogue
#pragma unroll
    for (int mt = 0; mt < 2; mt++) {
        int r = row0 + wm + mt * 16 + (lane >> 2);
#pragma unroll
        for (int nt = 0; nt < 4; nt++) {
            int cc = col0 + wn + nt * 8 + (lane & 3) * 2;
            if (HALFOUT) {
                __half* C = (__half*)Cv;
                *(__half2*)(C + (size_t)r * LDC + cc) =
                    __floats2half2_rn(c[mt][nt][0], c[mt][nt][1]);
                *(__half2*)(C + (size_t)(r + 8) * LDC + cc) =
                    __floats2half2_rn(c[mt][nt][2], c[mt][nt][3]);
            } else {
                float* C = (float*)Cv;
                float bx = 0.f, by = 0.f;
                if (HASBIAS) { bx = bias[cc]; by = bias[cc + 1]; }
                *(float2*)(C + (size_t)r * LDC + cc) =
                    make_float2(c[mt][nt][0] + bx, c[mt][nt][1] + by);
                *(float2*)(C + (size_t)(r + 8) * LDC + cc) =
                    make_float2(c[mt][nt][2] + bx, c[mt][nt][3] + by);
            }
        }
    }
}

// ---------------- fused attention kernel: one warp per point ----------------
// lane owns channels lane*4..lane*4+3 (one head: h = lane>>3).
// Pass-1 channel MLP + A2 projection run in half2; logit reduction packs the
// 4 head partials into 2 half2 regs (5 shfl total).
__global__ void __launch_bounds__(128) attn_kernel(const float* __restrict__ xyzs,
                                                   const int* __restrict__ kg,
                                                   const float* __restrict__ A2,
                                                   const float* __restrict__ P1,
                                                   const float* __restrict__ bp1,
                                                   const float* __restrict__ P2,
                                                   const float* __restrict__ bp2) {
    const unsigned FULL = 0xffffffffu;
    const int warp = threadIdx.x >> 5;
    const int lane = threadIdx.x & 31;
    const int pt   = blockIdx.x * 4 + warp;
    const int bN   = pt & ~(NN - 1);
    const int c0   = lane * 4;

    // ---- upfront: per-lane neighbor prep (lane l -> neighbor l&15) ----
    int rowoff_l;                 // (bN + idx) * NCAT  (fits in int32)
    float t0_l, t1_l, t2_l;       // pos-MLP hidden for neighbor l&15 (fp32, for S)
    __half2 t01h_l, t2h_l;        // packed for pass-1 shuffles
    {
        int idx = kg[(size_t)pt * NK + (lane & 15)];
        rowoff_l = (bN + idx) * NCAT;
        const float* nx = xyzs + (size_t)(bN + idx) * 3;
        float cx = xyzs[(size_t)pt * 3 + 0];
        float cy = xyzs[(size_t)pt * 3 + 1];
        float cz = xyzs[(size_t)pt * 3 + 2];
        float rx = cx - nx[0], ry = cy - nx[1], rz = cz - nx[2];
        t0_l = fmaxf(fmaf(rx, P1[0], fmaf(ry, P1[3], fmaf(rz, P1[6], bp1[0]))), 0.f);
        t1_l = fmaxf(fmaf(rx, P1[1], fmaf(ry, P1[4], fmaf(rz, P1[7], bp1[1]))), 0.f);
        t2_l = fmaxf(fmaf(rx, P1[2], fmaf(ry, P1[5], fmaf(rz, P1[8], bp1[2]))), 0.f);
        t01h_l = __floats2half2_rn(t0_l, t1_l);
        t2h_l  = __float2half2_rn(t2_l);
    }

    // per-lane channel constants (packed half2)
    __half2 hb0, hb1;               // hbase = QA + c1
    __half2 hp[3][2];               // P2A1 pairs
    __half2 a01[4], a23[4];         // A2[(c0+i)][0..1], [2..3]
    {
        uint2 qa = *(const uint2*)(g_QKVh + (size_t)pt * NCAT + c0);
        float4 c1 = *(const float4*)(g_c1 + c0);
        hb0 = __hadd2(*(__half2*)&qa.x, __floats2half2_rn(c1.x, c1.y));
        hb1 = __hadd2(*(__half2*)&qa.y, __floats2half2_rn(c1.z, c1.w));
#pragma unroll
        for (int r = 0; r < 3; r++) {
            float4 v = *(const float4*)(g_P2A1 + r * HD + c0);
            hp[r][0] = __floats2half2_rn(v.x, v.y);
            hp[r][1] = __floats2half2_rn(v.z, v.w);
        }
#pragma unroll
        for (int i = 0; i < 4; i++) {
            float4 a2v = *(const float4*)(A2 + (c0 + i) * 4);
            a01[i] = __floats2half2_rn(a2v.x, a2v.y);
            a23[i] = __floats2half2_rn(a2v.z, a2v.w);
        }
    }
    const __half2 z2 = __float2half2_rn(0.f);
    const bool hi = (lane & 16) != 0;

    float lk0 = 0.f, lk1 = 0.f;

    // ---- pass 1: per-neighbor logits (half2 math) ----
#pragma unroll
    for (int k = 0; k < NK; k++) {
        int rowoff = __shfl_sync(FULL, rowoff_l, k);
        __half2 t01 = shfl_h2(t01h_l, k);
        __half2 tb2 = shfl_h2(t2h_l, k);
        __half2 tb0 = __low2half2(t01);
        __half2 tb1 = __high2half2(t01);
        uint2 kau = *(const uint2*)(g_QKVh + rowoff + HD + c0);
        __half2 h0 = __hsub2(hb0, *(__half2*)&kau.x);
        __half2 h1 = __hsub2(hb1, *(__half2*)&kau.y);
        h0 = __hfma2(tb0, hp[0][0], h0);
        h0 = __hfma2(tb1, hp[1][0], h0);
        h0 = __hfma2(tb2, hp[2][0], h0);
        h1 = __hfma2(tb0, hp[0][1], h1);
        h1 = __hfma2(tb1, hp[1][1], h1);
        h1 = __hfma2(tb2, hp[2][1], h1);
        __half2 r0 = __hmax2(h0, z2);
        __half2 r1 = __hmax2(h1, z2);
        // A2 projection into packed head pairs
        __half2 q01 = z2, q23 = z2, b;
        b = __low2half2(r0);  q01 = __hfma2(b, a01[0], q01); q23 = __hfma2(b, a23[0], q23);
        b = __high2half2(r0); q01 = __hfma2(b, a01[1], q01); q23 = __hfma2(b, a23[1], q23);
        b = __low2half2(r1);  q01 = __hfma2(b, a01[2], q01); q23 = __hfma2(b, a23[2], q23);
        b = __high2half2(r1); q01 = __hfma2(b, a01[3], q01); q23 = __hfma2(b, a23[3], q23);
        // packed reduction: lo lanes end with (h0,h1), hi lanes with (h2,h3)
        __half2 sel = hi ? q01 : q23;
        __half2 oth = hi ? q23 : q01;
        __half2 u = __hadd2(oth, shfl_xor_h2(sel, 16));
        u = __hadd2(u, shfl_xor_h2(u, 8));
        u = __hadd2(u, shfl_xor_h2(u, 4));
        u = __hadd2(u, shfl_xor_h2(u, 2));
        u = __hadd2(u, shfl_xor_h2(u, 1));
        // head h lives at lanes 8h..8h+7: lane&8 selects high half
        float ww = (lane & 8) ? __high2float(u) : __low2float(u);
        if ((lane & 7) == (k & 7)) {
            if (k < 8) lk0 = ww; else lk1 = ww;
        }
    }

    // ---- softmax: head h in 8-lane group [8h, 8h+7], 2 logits/lane ----
    float mx = fmaxf(lk0, lk1);
    mx = fmaxf(mx, __shfl_xor_sync(FULL, mx, 4));
    mx = fmaxf(mx, __shfl_xor_sync(FULL, mx, 2));
    mx = fmaxf(mx, __shfl_xor_sync(FULL, mx, 1));
    float e0 = __expf(lk0 - mx), e1 = __expf(lk1 - mx);
    float s = e0 + e1;
    s += __shfl_xor_sync(FULL, s, 4);
    s += __shfl_xor_sync(FULL, s, 2);
    s += __shfl_xor_sync(FULL, s, 1);
    float inv = __fdividef(1.f, s);
    float a0 = e0 * inv, a1 = e1 * inv;   // attn(h=lane>>3, k=(lane&7)[+8])

    // ---- factored pe reduction: S_r(h) = sum_k attn(h,k)*t_r(k), S3 = sum_k attn ----
    float S0, S1, S2, S3;
    {
        int kk = lane & 7;
        float ua = __shfl_sync(FULL, t0_l, kk);
        float ub = __shfl_sync(FULL, t0_l, kk + 8);
        S0 = a0 * ua + a1 * ub;
        ua = __shfl_sync(FULL, t1_l, kk);
        ub = __shfl_sync(FULL, t1_l, kk + 8);
        S1 = a0 * ua + a1 * ub;
        ua = __shfl_sync(FULL, t2_l, kk);
        ub = __shfl_sync(FULL, t2_l, kk + 8);
        S2 = a0 * ua + a1 * ub;
        S3 = a0 + a1;
#pragma unroll
        for (int m = 4; m >= 1; m >>= 1) {
            S0 += __shfl_xor_sync(FULL, S0, m);
            S1 += __shfl_xor_sync(FULL, S1, m);
            S2 += __shfl_xor_sync(FULL, S2, m);
            S3 += __shfl_xor_sync(FULL, S3, m);
        }
    }

    // accv init = S0*P2row0 + S1*P2row1 + S2*P2row2 + S3*bp2
    float accv[4];
    {
        float4 v0 = *(const float4*)(P2 + 0 * HD + c0);
        float4 v1 = *(const float4*)(P2 + 1 * HD + c0);
        float4 v2 = *(const float4*)(P2 + 2 * HD + c0);
        float4 vb = *(const float4*)(bp2 + c0);
        accv[0] = fmaf(S0, v0.x, fmaf(S1, v1.x, fmaf(S2, v2.x, S3 * vb.x)));
        accv[1] = fmaf(S0, v0.y, fmaf(S1, v1.y, fmaf(S2, v2.y, S3 * vb.y)));
        accv[2] = fmaf(S0, v0.z, fmaf(S1, v1.z, fmaf(S2, v2.z, S3 * vb.z)));
        accv[3] = fmaf(S0, v0.w, fmaf(S1, v1.w, fmaf(S2, v2.w, S3 * vb.w)));
    }

    const int hsrc = lane & 24;   // 8 * head(lane)

    // ---- pass 2: weighted V reduce only (fp32 accum) ----
#pragma unroll
    for (int k = 0; k < NK; k++) {
        float asel = (k < 8) ? a0 : a1;
        float aw = __shfl_sync(FULL, asel, hsrc | (k & 7));
        int rowoff = __shfl_sync(FULL, rowoff_l, k);
        float4 vv = ldh4(g_QKVh + rowoff + 2 * HD + c0);
        accv[0] = fmaf(aw, vv.x, accv[0]);
        accv[1] = fmaf(aw, vv.y, accv[1]);
        accv[2] = fmaf(aw, vv.z, accv[2]);
        accv[3] = fmaf(aw, vv.w, accv[3]);
    }

    // write fused as fp16
    {
        uint2 o;
        *(__half2*)&o.x = __floats2half2_rn(accv[0], accv[1]);
        *(__half2*)&o.y = __floats2half2_rn(accv[2], accv[3]);
        *(uint2*)(g_fusedh + (size_t)pt * HD + c0) = o;
    }
}

// ======================= launch =============================================
extern "C" void kernel_launch(void* const* d_in, const int* in_sizes, int n_in,
                              void* d_out, int out_size) {
    const float* xyzs     = (const float*)d_in[0];
    const float* features = (const float*)d_in[1];
    const int*   kg       = (const int*)d_in[2];
    const float* Wk   = (const float*)d_in[3];
    const float* Wv   = (const float*)d_in[4];
    const float* Wq   = (const float*)d_in[5];
    const float* A1   = (const float*)d_in[6];
    const float* b1   = (const float*)d_in[7];
    const float* A2   = (const float*)d_in[8];
    const float* P1   = (const float*)d_in[10];
    const float* bp1  = (const float*)d_in[11];
    const float* P2   = (const float*)d_in[12];
    const float* bp2  = (const float*)d_in[13];
    const float* Wout = (const float*)d_in[14];
    const float* bout = (const float*)d_in[15];
    float* out = (float*)d_out;

    __half *pQKVh, *pFeath, *pWcatPh, *pWoutPh, *pFusedh;
    cudaGetSymbolAddress((void**)&pQKVh,   g_QKVh);
    cudaGetSymbolAddress((void**)&pFeath,  g_feath);
    cudaGetSymbolAddress((void**)&pWcatPh, g_WcatPh);
    cudaGetSymbolAddress((void**)&pWoutPh, g_WoutPh);
    cudaGetSymbolAddress((void**)&pFusedh, g_fusedh);

    const int conv_blks = (CONV_ITEMS + 383) / 384;
    setup_kernel<<<SETUP_BLKS + conv_blks, 384>>>(Wq, Wk, Wv, A1, P2, b1, bp2,
                                                  Wout, features);

    // QKV: [16384 x 64] @ [384 x 64]^T -> fp16 [16384 x 384]
    mma_gemm_kernel<CIN, CIN, CIN, NCAT, false, true>
        <<<dim3(NPTS / 64, NCAT / 64), 128>>>(pFeath, pWcatPh, nullptr, pQKVh);

    attn_kernel<<<NPTS / 4, 128>>>(xyzs, kg, A2, P1, bp1, P2, bp2);

    // out: [16384 x 128] @ [128 x 128]^T + bout -> fp32 [16384 x 128]
    mma_gemm_kernel<HD, HD, HD, COUT, true, false>
        <<<dim3(NPTS / 64, COUT / 64), 128>>>(pFusedh, pWoutPh, bout, out);
}

// round 12
// speedup vs baseline: 2.2813x; 1.0663x over previous
#include <cuda_runtime.h>
#include <cuda_fp16.h>
#include <cstdint>

#define NB   2
#define NN   8192
#define NK   16
#define HD   128
#define CIN  64
#define COUT 128
#define NPTS (NB * NN)   // 16384
#define NCAT 384         // QA|KA|V concatenated

// ---------------- helpers ----------------------------------------------------
__device__ __forceinline__ uint32_t smem_to_u32(const void* p) {
    uint32_t a;
    asm("{ .reg .u64 t; cvta.to.shared.u64 t, %1; cvt.u32.u64 %0, t; }"
        : "=r"(a) : "l"(p));
    return a;
}
#define LDSM_X4(r0, r1, r2, r3, addr) \
    asm volatile("ldmatrix.sync.aligned.m8n8.x4.shared.b16 {%0,%1,%2,%3}, [%4];" \
                 : "=r"(r0), "=r"(r1), "=r"(r2), "=r"(r3) : "r"(addr))
#define MMA_F16(c, a, b0, b1) \
    asm volatile("mma.sync.aligned.m16n8k16.row.col.f32.f16.f16.f32 " \
                 "{%0,%1,%2,%3}, {%4,%5,%6,%7}, {%8,%9}, {%0,%1,%2,%3};" \
                 : "+f"((c)[0]), "+f"((c)[1]), "+f"((c)[2]), "+f"((c)[3]) \
                 : "r"((a)[0]), "r"((a)[1]), "r"((a)[2]), "r"((a)[3]), \
                   "r"(b0), "r"(b1))
#define CP_ASYNC16(dst, src) \
    asm volatile("cp.async.cg.shared.global [%0], [%1], 16;" \
                 :: "r"(dst), "l"(src) : "memory")
#define CP_COMMIT() asm volatile("cp.async.commit_group;" ::: "memory")
#define CP_WAIT(n)  asm volatile("cp.async.wait_group %0;" :: "n"(n) : "memory")
#define SWZ(b) ((b) ^ (((b) >> 3) & 0x70))

__device__ __forceinline__ float4 ldh4(const __half* p) {
    uint2 u = *(const uint2*)p;
    float2 fa = __half22float2(*(__half2*)&u.x);
    float2 fb = __half22float2(*(__half2*)&u.y);
    return make_float4(fa.x, fa.y, fb.x, fb.y);
}
__device__ __forceinline__ __half2 shfl_h2(__half2 v, int src) {
    uint32_t u = *(uint32_t*)&v;
    u = __shfl_sync(0xffffffffu, u, src);
    return *(__half2*)&u;
}
__device__ __forceinline__ __half2 shfl_xor_h2(__half2 v, int m) {
    uint32_t u = *(uint32_t*)&v;
    u = __shfl_xor_sync(0xffffffffu, u, m);
    return *(__half2*)&u;
}

// ---------------- scratch globals --------------------------------------------
__device__ float g_P2A1[3 * HD];
__device__ float g_c1[HD];
__device__ __align__(16) __half g_QKVh[NPTS * NCAT];       // fp16 [QA|KA|V]
__device__ __align__(16) __half g_feath[NPTS * CIN];       // fp16 features
__device__ __align__(16) __half g_WcatPh[NCAT * CIN];      // fp16 [n][k] folded
__device__ __align__(16) __half g_WoutPh[HD * HD];         // fp16 [n][k]
__device__ __align__(16) __half g_fusedh[NPTS * HD];       // fp16 fused

// ---------------- setup + feature convert (merged, one launch) ---------------
#define SETUP_BLKS (CIN + 1 + HD)          // 193
#define CONV_ITEMS (NPTS * CIN / 4)        // 262144
__global__ void setup_kernel(const float* __restrict__ Wq, const float* __restrict__ Wk,
                             const float* __restrict__ Wv, const float* __restrict__ A1,
                             const float* __restrict__ P2, const float* __restrict__ b1,
                             const float* __restrict__ bp2, const float* __restrict__ Wout,
                             const float* __restrict__ feat) {
    int c = threadIdx.x;          // 0..383
    int blk = blockIdx.x;
    if (blk < CIN) {
        int r = blk;
        float acc;
        if (c < HD) {
            acc = 0.f;
            for (int j = 0; j < HD; j++) acc = fmaf(Wq[r * HD + j], A1[j * HD + c], acc);
        } else if (c < 2 * HD) {
            int cc = c - HD;
            acc = 0.f;
            for (int j = 0; j < HD; j++) acc = fmaf(Wk[r * HD + j], A1[j * HD + cc], acc);
        } else {
            acc = Wv[r * HD + (c - 2 * HD)];
        }
        g_WcatPh[c * CIN + r] = __float2half_rn(acc);
    } else if (blk == CIN) {
        if (c < HD) {
            for (int rr = 0; rr < 3; rr++) {
                float acc = 0.f;
                for (int j = 0; j < HD; j++) acc = fmaf(P2[rr * HD + j], A1[j * HD + c], acc);
                g_P2A1[rr * HD + c] = acc;
            }
            float acc = b1[c];
            for (int j = 0; j < HD; j++) acc = fmaf(bp2[j], A1[j * HD + c], acc);
            g_c1[c] = acc;
        }
    } else if (blk < SETUP_BLKS) {
        int n = blk - CIN - 1;    // 0..127
        if (c < HD)
            g_WoutPh[n * HD + c] = __float2half_rn(Wout[c * HD + n]);
    } else {
        int e = (blk - SETUP_BLKS) * 384 + c;
        if (e < CONV_ITEMS) {
            float4 v = ((const float4*)feat)[e];
            uint2 o;
            *(__half2*)&o.x = __floats2half2_rn(v.x, v.y);
            *(__half2*)&o.y = __floats2half2_rn(v.z, v.w);
            ((uint2*)g_feath)[e] = o;
        }
    }
}

// ---------------- fp16 mma GEMM, 2-stage cp.async pipeline --------------------
// Tile 32(M) x 64(N), 128 thr (4 warps), warp computes 16x32.
// wm = (wid&1)*16, wn = (wid>>1)*32. K chunked by 64, double-buffered.
template <int KTOT, int LDA, int LDB, int LDC, bool HASBIAS, bool HALFOUT>
__global__ void __launch_bounds__(128) mma_gemm_kernel(const __half* __restrict__ A,
                                                       const __half* __restrict__ B,
                                                       const float* __restrict__ bias,
                                                       void* __restrict__ Cv) {
    constexpr int NCH = KTOT / 64;
    __shared__ __align__(16) char sA[2][4096];   // 32 rows x 64 halves (swizzled)
    __shared__ __align__(16) char sB[2][8192];   // 64 rows x 64 halves

    const int tid = threadIdx.x, wid = tid >> 5, lane = tid & 31;
    const int row0 = blockIdx.x * 32, col0 = blockIdx.y * 64;
    const int wm = (wid & 1) * 16, wn = (wid >> 1) * 32;
    const uint32_t sAb = smem_to_u32(sA), sBb = smem_to_u32(sB);

    float c[4][4];
#pragma unroll
    for (int nt = 0; nt < 4; nt++)
#pragma unroll
        for (int q = 0; q < 4; q++) c[nt][q] = 0.f;

    const uint32_t lrow = lane & 15;
    const uint32_t lcb  = (lane >> 4) * 16;
    const int lr0 = tid >> 3, lc0 = tid & 7;     // for B loads (64 rows)
    const int lr0a = tid >> 3;                   // A rows 0..15 for u=0, +16 for u=1

    auto issue_load = [&](int ch, int st) {
        // A: 32 rows x 128B = 256 chunks, 2 per thread
#pragma unroll
        for (int u = 0; u < 2; u++) {
            int r = lr0a + u * 16;
            uint32_t off = SWZ((uint32_t)(r * 128 + lc0 * 16));
            CP_ASYNC16(sAb + st * 4096 + off,
                       A + (size_t)(row0 + r) * LDA + ch * 64 + lc0 * 8);
        }
        // B: 64 rows x 128B = 512 chunks, 4 per thread
#pragma unroll
        for (int u = 0; u < 4; u++) {
            int r = lr0 + u * 16;
            uint32_t off = SWZ((uint32_t)(r * 128 + lc0 * 16));
            CP_ASYNC16(sBb + st * 8192 + off,
                       B + (size_t)(col0 + r) * LDB + ch * 64 + lc0 * 8);
        }
        CP_COMMIT();
    };

    issue_load(0, 0);

#pragma unroll
    for (int ch = 0; ch < NCH; ch++) {
        const int st = ch & 1;
        if (ch + 1 < NCH) {
            issue_load(ch + 1, st ^ 1);
            CP_WAIT(1);
        } else {
            CP_WAIT(0);
        }
        __syncthreads();

#pragma unroll
        for (int k16 = 0; k16 < 4; k16++) {
            uint32_t a[4], bf[2][4];
            {
                uint32_t b = SWZ((wm + lrow) * 128 + k16 * 32 + lcb);
                LDSM_X4(a[0], a[1], a[2], a[3], sAb + st * 4096 + b);
            }
#pragma unroll
            for (int np = 0; np < 2; np++) {
                uint32_t b = SWZ((wn + np * 16 + lrow) * 128 + k16 * 32 + lcb);
                LDSM_X4(bf[np][0], bf[np][1], bf[np][2], bf[np][3], sBb + st * 8192 + b);
            }
#pragma unroll
            for (int nt = 0; nt < 4; nt++)
                MMA_F16(c[nt], a, bf[nt >> 1][nt & 1], bf[nt >> 1][(nt & 1) + 2]);
        }
        if (ch + 1 < NCH) __syncthreads();
    }

    // epilogue
    {
        int r = row0 + wm + (lane >> 2);
#pragma unroll
        for (int nt = 0; nt < 4; nt++) {
            int cc = col0 + wn + nt * 8 + (lane & 3) * 2;
            if (HALFOUT) {
                __half* C = (__half*)Cv;
                *(__half2*)(C + (size_t)r * LDC + cc) =
                    __floats2half2_rn(c[nt][0], c[nt][1]);
                *(__half2*)(C + (size_t)(r + 8) * LDC + cc) =
                    __floats2half2_rn(c[nt][2], c[nt][3]);
            } else {
                float* C = (float*)Cv;
                float bx = 0.f, by = 0.f;
                if (HASBIAS) { bx = bias[cc]; by = bias[cc + 1]; }
                *(float2*)(C + (size_t)r * LDC + cc) =
                    make_float2(c[nt][0] + bx, c[nt][1] + by);
                *(float2*)(C + (size_t)(r + 8) * LDC + cc) =
                    make_float2(c[nt][2] + bx, c[nt][3] + by);
            }
        }
    }
}

// ---------------- fused attention kernel: one warp per point ----------------
__global__ void __launch_bounds__(128, 7) attn_kernel(const float* __restrict__ xyzs,
                                                      const int* __restrict__ kg,
                                                      const float* __restrict__ A2,
                                                      const float* __restrict__ P1,
                                                      const float* __restrict__ bp1,
                                                      const float* __restrict__ P2,
                                                      const float* __restrict__ bp2) {
    const unsigned FULL = 0xffffffffu;
    const int warp = threadIdx.x >> 5;
    const int lane = threadIdx.x & 31;
    const int pt   = blockIdx.x * 4 + warp;
    const int bN   = pt & ~(NN - 1);
    const int c0   = lane * 4;

    // ---- upfront: per-lane neighbor prep (lane l -> neighbor l&15) ----
    int rowoff_l;
    float t0_l, t1_l, t2_l;
    __half2 t01h_l, t2h_l;
    {
        int idx = kg[(size_t)pt * NK + (lane & 15)];
        rowoff_l = (bN + idx) * NCAT;
        const float* nx = xyzs + (size_t)(bN + idx) * 3;
        float cx = xyzs[(size_t)pt * 3 + 0];
        float cy = xyzs[(size_t)pt * 3 + 1];
        float cz = xyzs[(size_t)pt * 3 + 2];
        float rx = cx - nx[0], ry = cy - nx[1], rz = cz - nx[2];
        t0_l = fmaxf(fmaf(rx, P1[0], fmaf(ry, P1[3], fmaf(rz, P1[6], bp1[0]))), 0.f);
        t1_l = fmaxf(fmaf(rx, P1[1], fmaf(ry, P1[4], fmaf(rz, P1[7], bp1[1]))), 0.f);
        t2_l = fmaxf(fmaf(rx, P1[2], fmaf(ry, P1[5], fmaf(rz, P1[8], bp1[2]))), 0.f);
        t01h_l = __floats2half2_rn(t0_l, t1_l);
        t2h_l  = __float2half2_rn(t2_l);
    }

    // per-lane channel constants (packed half2)
    __half2 hb0, hb1;
    __half2 hp[3][2];
    __half2 a01[4], a23[4];
    {
        uint2 qa = *(const uint2*)(g_QKVh + (size_t)pt * NCAT + c0);
        float4 c1 = *(const float4*)(g_c1 + c0);
        hb0 = __hadd2(*(__half2*)&qa.x, __floats2half2_rn(c1.x, c1.y));
        hb1 = __hadd2(*(__half2*)&qa.y, __floats2half2_rn(c1.z, c1.w));
#pragma unroll
        for (int r = 0; r < 3; r++) {
            float4 v = *(const float4*)(g_P2A1 + r * HD + c0);
            hp[r][0] = __floats2half2_rn(v.x, v.y);
            hp[r][1] = __floats2half2_rn(v.z, v.w);
        }
#pragma unroll
        for (int i = 0; i < 4; i++) {
            float4 a2v = *(const float4*)(A2 + (c0 + i) * 4);
            a01[i] = __floats2half2_rn(a2v.x, a2v.y);
            a23[i] = __floats2half2_rn(a2v.z, a2v.w);
        }
    }
    const __half2 z2 = __float2half2_rn(0.f);
    const bool hi = (lane & 16) != 0;

    __half2 lku0 = z2, lku1 = z2;   // packed logits; extract after loop

    // ---- pass 1: per-neighbor logits (half2 math) ----
#pragma unroll
    for (int k = 0; k < NK; k++) {
        int rowoff = __shfl_sync(FULL, rowoff_l, k);
        __half2 t01 = shfl_h2(t01h_l, k);
        __half2 tb2 = shfl_h2(t2h_l, k);
        __half2 tb0 = __low2half2(t01);
        __half2 tb1 = __high2half2(t01);
        uint2 kau = *(const uint2*)(g_QKVh + rowoff + HD + c0);
        __half2 h0 = __hsub2(hb0, *(__half2*)&kau.x);
        __half2 h1 = __hsub2(hb1, *(__half2*)&kau.y);
        h0 = __hfma2(tb0, hp[0][0], h0);
        h0 = __hfma2(tb1, hp[1][0], h0);
        h0 = __hfma2(tb2, hp[2][0], h0);
        h1 = __hfma2(tb0, hp[0][1], h1);
        h1 = __hfma2(tb1, hp[1][1], h1);
        h1 = __hfma2(tb2, hp[2][1], h1);
        __half2 r0 = __hmax2(h0, z2);
        __half2 r1 = __hmax2(h1, z2);
        __half2 q01 = z2, q23 = z2, b;
        b = __low2half2(r0);  q01 = __hfma2(b, a01[0], q01); q23 = __hfma2(b, a23[0], q23);
        b = __high2half2(r0); q01 = __hfma2(b, a01[1], q01); q23 = __hfma2(b, a23[1], q23);
        b = __low2half2(r1);  q01 = __hfma2(b, a01[2], q01); q23 = __hfma2(b, a23[2], q23);
        b = __high2half2(r1); q01 = __hfma2(b, a01[3], q01); q23 = __hfma2(b, a23[3], q23);
        __half2 sel = hi ? q01 : q23;
        __half2 oth = hi ? q23 : q01;
        __half2 u = __hadd2(oth, shfl_xor_h2(sel, 16));
        u = __hadd2(u, shfl_xor_h2(u, 8));
        u = __hadd2(u, shfl_xor_h2(u, 4));
        u = __hadd2(u, shfl_xor_h2(u, 2));
        u = __hadd2(u, shfl_xor_h2(u, 1));
        if ((lane & 7) == (k & 7)) {
            if (k < 8) lku0 = u; else lku1 = u;
        }
    }
    // extract this lane's head (lane&8 -> high half)
    float lk0 = (lane & 8) ? __high2float(lku0) : __low2float(lku0);
    float lk1 = (lane & 8) ? __high2float(lku1) : __low2float(lku1);

    // ---- softmax: head h in 8-lane group [8h, 8h+7], 2 logits/lane ----
    float mx = fmaxf(lk0, lk1);
    mx = fmaxf(mx, __shfl_xor_sync(FULL, mx, 4));
    mx = fmaxf(mx, __shfl_xor_sync(FULL, mx, 2));
    mx = fmaxf(mx, __shfl_xor_sync(FULL, mx, 1));
    float e0 = __expf(lk0 - mx), e1 = __expf(lk1 - mx);
    float s = e0 + e1;
    s += __shfl_xor_sync(FULL, s, 4);
    s += __shfl_xor_sync(FULL, s, 2);
    s += __shfl_xor_sync(FULL, s, 1);
    float inv = __fdividef(1.f, s);
    float a0 = e0 * inv, a1 = e1 * inv;

    // ---- factored pe reduction ----
    float S0, S1, S2, S3;
    {
        int kk = lane & 7;
        float ua = __shfl_sync(FULL, t0_l, kk);
        float ub = __shfl_sync(FULL, t0_l, kk + 8);
        S0 = a0 * ua + a1 * ub;
        ua = __shfl_sync(FULL, t1_l, kk);
        ub = __shfl_sync(FULL, t1_l, kk + 8);
        S1 = a0 * ua + a1 * ub;
        ua = __shfl_sync(FULL, t2_l, kk);
        ub = __shfl_sync(FULL, t2_l, kk + 8);
        S2 = a0 * ua + a1 * ub;
        S3 = a0 + a1;
#pragma unroll
        for (int m = 4; m >= 1; m >>= 1) {
            S0 += __shfl_xor_sync(FULL, S0, m);
            S1 += __shfl_xor_sync(FULL, S1, m);
            S2 += __shfl_xor_sync(FULL, S2, m);
            S3 += __shfl_xor_sync(FULL, S3, m);
        }
    }

    float accv[4];
    {
        float4 v0 = *(const float4*)(P2 + 0 * HD + c0);
        float4 v1 = *(const float4*)(P2 + 1 * HD + c0);
        float4 v2 = *(const float4*)(P2 + 2 * HD + c0);
        float4 vb = *(const float4*)(bp2 + c0);
        accv[0] = fmaf(S0, v0.x, fmaf(S1, v1.x, fmaf(S2, v2.x, S3 * vb.x)));
        accv[1] = fmaf(S0, v0.y, fmaf(S1, v1.y, fmaf(S2, v2.y, S3 * vb.y)));
        accv[2] = fmaf(S0, v0.z, fmaf(S1, v1.z, fmaf(S2, v2.z, S3 * vb.z)));
        accv[3] = fmaf(S0, v0.w, fmaf(S1, v1.w, fmaf(S2, v2.w, S3 * vb.w)));
    }

    const int hsrc = lane & 24;

    // ---- pass 2: weighted V reduce ----
#pragma unroll
    for (int k = 0; k < NK; k++) {
        float asel = (k < 8) ? a0 : a1;
        float aw = __shfl_sync(FULL, asel, hsrc | (k & 7));
        int rowoff = __shfl_sync(FULL, rowoff_l, k);
        float4 vv = ldh4(g_QKVh + rowoff + 2 * HD + c0);
        accv[0] = fmaf(aw, vv.x, accv[0]);
        accv[1] = fmaf(aw, vv.y, accv[1]);
        accv[2] = fmaf(aw, vv.z, accv[2]);
        accv[3] = fmaf(aw, vv.w, accv[3]);
    }

    {
        uint2 o;
        *(__half2*)&o.x = __floats2half2_rn(accv[0], accv[1]);
        *(__half2*)&o.y = __floats2half2_rn(accv[2], accv[3]);
        *(uint2*)(g_fusedh + (size_t)pt * HD + c0) = o;
    }
}

// ======================= launch =============================================
extern "C" void kernel_launch(void* const* d_in, const int* in_sizes, int n_in,
                              void* d_out, int out_size) {
    const float* xyzs     = (const float*)d_in[0];
    const float* features = (const float*)d_in[1];
    const int*   kg       = (const int*)d_in[2];
    const float* Wk   = (const float*)d_in[3];
    const float* Wv   = (const float*)d_in[4];
    const float* Wq   = (const float*)d_in[5];
    const float* A1   = (const float*)d_in[6];
    const float* b1   = (const float*)d_in[7];
    const float* A2   = (const float*)d_in[8];
    const float* P1   = (const float*)d_in[10];
    const float* bp1  = (const float*)d_in[11];
    const float* P2   = (const float*)d_in[12];
    const float* bp2  = (const float*)d_in[13];
    const float* Wout = (const float*)d_in[14];
    const float* bout = (const float*)d_in[15];
    float* out = (float*)d_out;

    __half *pQKVh, *pFeath, *pWcatPh, *pWoutPh, *pFusedh;
    cudaGetSymbolAddress((void**)&pQKVh,   g_QKVh);
    cudaGetSymbolAddress((void**)&pFeath,  g_feath);
    cudaGetSymbolAddress((void**)&pWcatPh, g_WcatPh);
    cudaGetSymbolAddress((void**)&pWoutPh, g_WoutPh);
    cudaGetSymbolAddress((void**)&pFusedh, g_fusedh);

    const int conv_blks = (CONV_ITEMS + 383) / 384;
    setup_kernel<<<SETUP_BLKS + conv_blks, 384>>>(Wq, Wk, Wv, A1, P2, b1, bp2,
                                                  Wout, features);

    // QKV: [16384 x 64] @ [384 x 64]^T -> fp16 [16384 x 384]   (3072 blocks)
    mma_gemm_kernel<CIN, CIN, CIN, NCAT, false, true>
        <<<dim3(NPTS / 32, NCAT / 64), 128>>>(pFeath, pWcatPh, nullptr, pQKVh);

    attn_kernel<<<NPTS / 4, 128>>>(xyzs, kg, A2, P1, bp1, P2, bp2);

    // out: [16384 x 128] @ [128 x 128]^T + bout -> fp32        (1024 blocks)
    mma_gemm_kernel<HD, HD, HD, COUT, true, false>
        <<<dim3(NPTS / 32, COUT / 64), 128>>>(pFusedh, pWoutPh, bout, out);
}